// round 7
// baseline (speedup 1.0000x reference)
#include <cuda_runtime.h>
#include <cuda_fp16.h>

#define NN 768
#define CC 384
#define CZd 128
#define HHd 16
#define CHD 24
#define NP (NN*NN)
#define INFV 1e9f
#define EPSV 1e-5f

typedef unsigned long long u64;
typedef unsigned int u32;

// ------------------------- device scratch (no runtime alloc) ----------------
__device__ float g_q[NN*CC];
__device__ float g_k[NN*CC];
__device__ float g_v[NN*CC];
__device__ float g_g[NN*CC];
__device__ float g_o[NN*CC];
__device__ float g_Wpp[2048];          // packed [c2][h][2] : {Wp[2c][h], Wp[2c+1][h]}
__device__ float g_S[HHd];
__device__ float g_Cb[HHd];
__device__ __half g_bias[(size_t)HHd*NP];   // [h][i*768 + j]

// ------------------------- packed f32x2 helpers (sm_103a) -------------------
__device__ __forceinline__ u64 pk2(float x, float y){
    u64 r; asm("mov.b64 %0,{%1,%2};" : "=l"(r) : "r"(__float_as_uint(x)), "r"(__float_as_uint(y))); return r;
}
__device__ __forceinline__ float2 up2(u64 v){
    u32 a,b; asm("mov.b64 {%0,%1},%2;" : "=r"(a), "=r"(b) : "l"(v));
    return make_float2(__uint_as_float(a), __uint_as_float(b));
}
__device__ __forceinline__ u64 ffma2(u64 a, u64 b, u64 c){
    u64 d; asm("fma.rn.f32x2 %0,%1,%2,%3;" : "=l"(d) : "l"(a), "l"(b), "l"(c)); return d;
}
__device__ __forceinline__ u64 fmul2(u64 a, u64 b){
    u64 d; asm("mul.rn.f32x2 %0,%1,%2;" : "=l"(d) : "l"(a), "l"(b)); return d;
}
__device__ __forceinline__ u64 fadd2(u64 a, u64 b){
    u64 d; asm("add.rn.f32x2 %0,%1,%2;" : "=l"(d) : "l"(a), "l"(b)); return d;
}
__device__ __forceinline__ float sigmoidf_(float x){ return 1.f/(1.f + __expf(-x)); }

// ------------------------- kernel 1: fold LN(z) weights (R2 version) --------
__global__ void k_prep(const float* __restrict__ lnzw, const float* __restrict__ lnzb,
                       const float* __restrict__ Wz){
    __shared__ float sw[128][17];
    __shared__ float sb[128][17];
    int c = threadIdx.x;   // 0..127
    float w = lnzw[c], b = lnzb[c];
    #pragma unroll
    for(int h=0; h<16; h++){
        float wz = Wz[c*16 + h];
        float wp = w*wz;
        sw[c][h] = wp;
        sb[c][h] = b*wz;
        g_Wpp[(c>>1)*32 + h*2 + (c&1)] = wp;
    }
    __syncthreads();
    if(c < 16){
        float s = 0.f, cb = 0.f;
        for(int j=0; j<128; j++){ s += sw[j][c]; cb += sb[j][c]; }
        g_S[c] = s; g_Cb[c] = cb;
    }
}

// ------------------------- kernel 2: pair bias (R2 version, measured 98us) --
// grid (6, 768): blockIdx.y = i, blockIdx.x = j-tile of 128. 128 threads.
__global__ void __launch_bounds__(128) k_bias(const float* __restrict__ z){
    __shared__ __align__(16) float zs[128*68];    // 128 j rows x 64 c (per phase), pad 68
    __shared__ __align__(16) float swp[2048];     // packed Wp
    __shared__ float smu[128], srs[128];
    __shared__ float sS[16], sCb[16];
    int t = threadIdx.x;
    int i  = blockIdx.y;
    int j0 = blockIdx.x*128;
    #pragma unroll
    for(int r=0; r<16; r++) swp[r*128 + t] = g_Wpp[r*128 + t];

    const float* zbase = z + ((size_t)i*NN + j0)*CZd;
    float sum = 0.f, ssq = 0.f;
    u64 acc[16];
    #pragma unroll
    for(int q=0; q<16; q++) acc[q] = 0ull;
    int hg = t & 3, jg = t >> 2;

    #pragma unroll
    for(int p=0; p<2; p++){
        __syncthreads();
        // cooperative coalesced load of 128 j x 64 c (half of CZ)
        #pragma unroll
        for(int r=0; r<16; r++){
            int idx = t + 128*r;
            int j = idx >> 4, c4 = idx & 15;
            float4 zv = *(const float4*)(zbase + (size_t)j*CZd + p*64 + c4*4);
            *(float4*)&zs[j*68 + c4*4] = zv;
        }
        __syncthreads();
        // stats for j = t
        #pragma unroll
        for(int c2=0; c2<32; c2++){
            float2 zz = up2(*(const u64*)&zs[t*68 + 2*c2]);
            sum += zz.x + zz.y;
            ssq = fmaf(zz.x, zz.x, ssq); ssq = fmaf(zz.y, zz.y, ssq);
        }
        // dots: 4 j (stride 32) x 4 h per thread
        const float* wbase = swp + p*32*32 + hg*8;
        #pragma unroll 4
        for(int c2=0; c2<32; c2++){
            const u64* wr = (const u64*)(wbase + c2*32);
            u64 w0 = wr[0], w1 = wr[1], w2 = wr[2], w3 = wr[3];
            #pragma unroll
            for(int s4=0; s4<4; s4++){
                u64 zv = *(const u64*)&zs[(jg + 32*s4)*68 + 2*c2];
                acc[s4*4+0] = ffma2(zv, w0, acc[s4*4+0]);
                acc[s4*4+1] = ffma2(zv, w1, acc[s4*4+1]);
                acc[s4*4+2] = ffma2(zv, w2, acc[s4*4+2]);
                acc[s4*4+3] = ffma2(zv, w3, acc[s4*4+3]);
            }
        }
    }
    float mu = sum * (1.f/128.f);
    float rs = rsqrtf(ssq*(1.f/128.f) - mu*mu + EPSV);
    smu[t] = mu; srs[t] = rs;
    if(t < 16){ sS[t] = g_S[t]; sCb[t] = g_Cb[t]; }
    __syncthreads();

    // finalize into half staging (reuse zs memory)
    __half* sh = (__half*)zs;
    #pragma unroll
    for(int s4=0; s4<4; s4++){
        int j = jg + 32*s4;
        float m_ = smu[j], r_ = srs[j];
        #pragma unroll
        for(int hi=0; hi<4; hi++){
            int h = hg*4 + hi;
            float2 d = up2(acc[s4*4+hi]);
            float bv = r_*((d.x + d.y) - m_*sS[h]) + sCb[h];
            sh[h*128 + j] = __float2half(bv);
        }
    }
    __syncthreads();
    const u32* sh2 = (const u32*)sh;
    #pragma unroll
    for(int r=0; r<8; r++){
        int lin = r*128 + t;
        int h = lin >> 6, j2 = lin & 63;
        *(u32*)&g_bias[(size_t)h*NP + (size_t)i*NN + j0 + j2*2] = sh2[h*64 + j2];
    }
}

// ------------------------- kernel 3: QKVG projections (LN fused) ------------
// grid (6, 12, 4), 256 threads. C = LN(a) @ W, +bg for z==3.
__global__ void __launch_bounds__(256) k_proj(const float* __restrict__ a,
                                              const float* __restrict__ lnaw,
                                              const float* __restrict__ lnab,
                                              const float* __restrict__ Wq,
                                              const float* __restrict__ Wk2,
                                              const float* __restrict__ Wv2,
                                              const float* __restrict__ Wg2,
                                              const float* __restrict__ bg){
    __shared__ __align__(16) float As[64*36];
    __shared__ __align__(16) float Bs[32*68];
    __shared__ float smu[64], srs[64];
    int t = threadIdx.x;
    int warp = t >> 5, lane = t & 31;
    int n0 = blockIdx.x*64, m0 = blockIdx.y*64, zz = blockIdx.z;
    const float* W = (zz==0) ? Wq : (zz==1) ? Wk2 : (zz==2) ? Wv2 : Wg2;
    float* Cd = (zz==0) ? g_q : (zz==1) ? g_k : (zz==2) ? g_v : g_g;

    // LN stats: 8 warps x 8 rows
    #pragma unroll
    for(int rr=0; rr<8; rr++){
        int row = m0 + warp*8 + rr;
        const float* ar = a + (size_t)row*CC;
        float s = 0.f, ss = 0.f;
        #pragma unroll
        for(int r=0; r<12; r++){ float v = ar[lane + r*32]; s += v; ss = fmaf(v,v,ss); }
        #pragma unroll
        for(int o=16; o; o>>=1){ s += __shfl_xor_sync(~0u,s,o); ss += __shfl_xor_sync(~0u,ss,o); }
        if(lane == 0){
            float mu = s*(1.f/CC);
            smu[warp*8+rr] = mu;
            srs[warp*8+rr] = rsqrtf(ss*(1.f/CC) - mu*mu + EPSV);
        }
    }
    __syncthreads();

    u64 acc[4][2];
    #pragma unroll
    for(int r=0;r<4;r++){ acc[r][0]=0; acc[r][1]=0; }
    int tm = t & 15, tn = t >> 4;

    for(int k0=0; k0<CC; k0+=32){
        __syncthreads();
        #pragma unroll
        for(int r=0; r<2; r++){
            int idx = t + 256*r;
            int row = idx >> 3, c4 = idx & 7;
            float4 av = *(const float4*)&a[(size_t)(m0+row)*CC + k0 + c4*4];
            float4 wv = *(const float4*)&lnaw[k0 + c4*4];
            float4 bv = *(const float4*)&lnab[k0 + c4*4];
            float mu = smu[row], rsg = srs[row];
            av.x = (av.x - mu)*rsg*wv.x + bv.x;
            av.y = (av.y - mu)*rsg*wv.y + bv.y;
            av.z = (av.z - mu)*rsg*wv.z + bv.z;
            av.w = (av.w - mu)*rsg*wv.w + bv.w;
            *(float4*)&As[row*36 + c4*4] = av;
            int kr = idx >> 4, n4 = idx & 15;
            float4 bw = *(const float4*)&W[(size_t)(k0+kr)*CC + n0 + n4*4];
            *(float4*)&Bs[kr*68 + n4*4] = bw;
        }
        __syncthreads();
        #pragma unroll 8
        for(int kk=0; kk<32; kk++){
            u64 b0 = *(const u64*)&Bs[kk*68 + tn*4 + 0];
            u64 b1 = *(const u64*)&Bs[kk*68 + tn*4 + 2];
            #pragma unroll
            for(int r=0; r<4; r++){
                float av = As[(tm + 16*r)*36 + kk];
                u64 a2 = pk2(av, av);
                acc[r][0] = ffma2(a2, b0, acc[r][0]);
                acc[r][1] = ffma2(a2, b1, acc[r][1]);
            }
        }
    }
    #pragma unroll
    for(int r=0; r<4; r++){
        int m = m0 + tm + 16*r;
        #pragma unroll
        for(int p=0; p<2; p++){
            int n = n0 + tn*4 + 2*p;
            float2 vv = up2(acc[r][p]);
            if(zz == 3){ vv.x += bg[n]; vv.y += bg[n+1]; }
            *(float2*)&Cd[(size_t)m*CC + n] = vv;
        }
    }
}

// ------------------------- kernel 4: attention -------------------------------
// grid (48, 16): blockIdx.x = q-tile of 16, blockIdx.y = h. 256 threads.
// 16-way k-split per q; tile-batched scores; smem-staged fp16 bias + mask.
__global__ void __launch_bounds__(256) k_attn(const float* __restrict__ mask){
    __shared__ __align__(16) float qs[16*26];
    __shared__ __align__(16) float ks[64*26];
    __shared__ __align__(16) float vs[64*26];
    __shared__ float sbf[16*64];
    __shared__ float smb[NN];
    int t = threadIdx.x;
    int h = blockIdx.y, q0 = blockIdx.x*16;
    const float scale = 0.20412414523193154f;  // 24^-0.5

    for(int idx=t; idx<16*24; idx+=256){
        int qq = idx/24, c = idx - qq*24;
        qs[qq*26 + c] = g_q[(size_t)(q0+qq)*CC + h*CHD + c] * scale;
    }
    for(int idx=t; idx<NN; idx+=256) smb[idx] = INFV*(mask[idx] - 1.f);
    __syncthreads();

    int qq = t >> 4, kg = t & 15;
    u64 qv[12];
    #pragma unroll
    for(int i2=0; i2<12; i2++) qv[i2] = *(const u64*)&qs[qq*26 + 2*i2];

    float mx = -1e30f, l = 0.f;
    u64 acc[12];
    #pragma unroll
    for(int i2=0; i2<12; i2++) acc[i2] = 0ull;
    const size_t hNP = (size_t)h*NP;

    for(int kt=0; kt<NN; kt+=64){
        __syncthreads();
        for(int idx=t; idx<64*24; idx+=256){
            int kk = idx/24, c = idx - kk*24;
            ks[kk*26 + c] = g_k[(size_t)(kt+kk)*CC + h*CHD + c];
            vs[kk*26 + c] = g_v[(size_t)(kt+kk)*CC + h*CHD + c];
        }
        // stage bias tile: 16 q x 64 k halves -> fp32 with mask folded
        #pragma unroll
        for(int r=0; r<2; r++){
            int idx = t + 256*r;          // 0..511
            int q = idx >> 5, k2 = idx & 31;
            u32 pv = *(const u32*)&g_bias[hNP + (size_t)(q0+q)*NN + kt + 2*k2];
            __half2 hh = *(__half2*)&pv;
            float2 fv = __half22float2(hh);
            sbf[q*64 + 2*k2]     = fv.x + smb[kt + 2*k2];
            sbf[q*64 + 2*k2 + 1] = fv.y + smb[kt + 2*k2 + 1];
        }
        __syncthreads();

        // phase 1: 4 independent score chains
        float sarr[4];
        #pragma unroll
        for(int ii=0; ii<4; ii++){
            int kk = kg + ii*16;
            u64 d2 = 0ull;
            #pragma unroll
            for(int i2=0; i2<12; i2++) d2 = ffma2(qv[i2], *(const u64*)&ks[kk*26 + 2*i2], d2);
            float2 dd = up2(d2);
            sarr[ii] = dd.x + dd.y + sbf[qq*64 + kk];
        }
        // phase 2: one max update per tile
        float tmax = fmaxf(fmaxf(sarr[0], sarr[1]), fmaxf(sarr[2], sarr[3]));
        if(tmax > mx){
            float f = __expf(mx - tmax);
            l *= f;
            u64 f2 = pk2(f, f);
            #pragma unroll
            for(int i2=0; i2<12; i2++) acc[i2] = fmul2(acc[i2], f2);
            mx = tmax;
        }
        // phase 3: independent exp + PV
        #pragma unroll
        for(int ii=0; ii<4; ii++){
            int kk = kg + ii*16;
            float e = __expf(sarr[ii] - mx);
            l += e;
            u64 e2 = pk2(e, e);
            #pragma unroll
            for(int i2=0; i2<12; i2++) acc[i2] = ffma2(*(const u64*)&vs[kk*26 + 2*i2], e2, acc[i2]);
        }
    }
    // merge the 16 lanes that share a q
    #pragma unroll
    for(int off=1; off<16; off<<=1){
        float om = __shfl_xor_sync(~0u, mx, off);
        float ol = __shfl_xor_sync(~0u, l,  off);
        float nm = fmaxf(mx, om);
        float fs = __expf(mx - nm), fo = __expf(om - nm);
        l = l*fs + ol*fo;
        u64 fs2 = pk2(fs, fs), fo2 = pk2(fo, fo);
        #pragma unroll
        for(int i2=0; i2<12; i2++){
            float2 av = up2(acc[i2]);
            float ox = __shfl_xor_sync(~0u, av.x, off);
            float oy = __shfl_xor_sync(~0u, av.y, off);
            acc[i2] = fadd2(fmul2(acc[i2], fs2), fmul2(pk2(ox, oy), fo2));
        }
        mx = nm;
    }
    if(kg == 0){
        float inv = 1.f / l;
        u64 iv = pk2(inv, inv);
        float* op = g_o + (size_t)(q0+qq)*CC + h*CHD;
        #pragma unroll
        for(int i2=0; i2<12; i2++){
            float2 vv = up2(fmul2(acc[i2], iv));
            *(float2*)&op[2*i2] = vv;
        }
    }
}

// ------------------------- kernel 5: gated output projection ----------------
__global__ void __launch_bounds__(128) k_oproj(const float* __restrict__ Wo,
                                               const float* __restrict__ bo,
                                               float* __restrict__ out){
    __shared__ __align__(16) float As[64*36];
    __shared__ __align__(16) float Bs[32*68];
    int t = threadIdx.x;
    int n0 = blockIdx.x*64, m0 = blockIdx.y*64;
    u64 acc[4][4];
    #pragma unroll
    for(int r=0;r<4;r++){ acc[r][0]=0; acc[r][1]=0; acc[r][2]=0; acc[r][3]=0; }
    int tm = t & 15, tn = t >> 4;

    for(int k0=0; k0<CC; k0+=32){
        __syncthreads();
        #pragma unroll
        for(int r=0; r<4; r++){
            int idx = t + 128*r;
            int row = idx >> 3, c4 = idx & 7;
            size_t aoff = (size_t)(m0+row)*CC + k0 + c4*4;
            float4 ov = *(const float4*)&g_o[aoff];
            float4 gv = *(const float4*)&g_g[aoff];
            float4 av;
            av.x = ov.x * sigmoidf_(gv.x);
            av.y = ov.y * sigmoidf_(gv.y);
            av.z = ov.z * sigmoidf_(gv.z);
            av.w = ov.w * sigmoidf_(gv.w);
            *(float4*)&As[row*36 + c4*4] = av;
            int kr = idx >> 4, n4 = idx & 15;
            float4 bv = *(const float4*)&Wo[(size_t)(k0+kr)*CC + n0 + n4*4];
            *(float4*)&Bs[kr*68 + n4*4] = bv;
        }
        __syncthreads();
        #pragma unroll 8
        for(int kk=0; kk<32; kk++){
            u64 b0 = *(const u64*)&Bs[kk*68 + tn*8 + 0];
            u64 b1 = *(const u64*)&Bs[kk*68 + tn*8 + 2];
            u64 b2 = *(const u64*)&Bs[kk*68 + tn*8 + 4];
            u64 b3 = *(const u64*)&Bs[kk*68 + tn*8 + 6];
            #pragma unroll
            for(int r=0; r<4; r++){
                float av = As[(tm + 16*r)*36 + kk];
                u64 a2 = pk2(av, av);
                acc[r][0] = ffma2(a2, b0, acc[r][0]);
                acc[r][1] = ffma2(a2, b1, acc[r][1]);
                acc[r][2] = ffma2(a2, b2, acc[r][2]);
                acc[r][3] = ffma2(a2, b3, acc[r][3]);
            }
        }
    }
    #pragma unroll
    for(int r=0; r<4; r++){
        int m = m0 + tm + 16*r;
        #pragma unroll
        for(int p=0; p<4; p++){
            int n = n0 + tn*8 + 2*p;
            float2 vv = up2(acc[r][p]);
            vv.x += bo[n]; vv.y += bo[n+1];
            *(float2*)&out[(size_t)m*CC + n] = vv;
        }
    }
}

// ------------------------- launch -------------------------------------------
extern "C" void kernel_launch(void* const* d_in, const int* in_sizes, int n_in,
                              void* d_out, int out_size){
    const float* a     = (const float*)d_in[0];
    const float* z     = (const float*)d_in[1];
    const float* mask  = (const float*)d_in[2];
    const float* lnaw  = (const float*)d_in[3];
    const float* lnab  = (const float*)d_in[4];
    const float* lnzw  = (const float*)d_in[5];
    const float* lnzb  = (const float*)d_in[6];
    const float* Wz    = (const float*)d_in[7];
    const float* Wq    = (const float*)d_in[8];
    const float* Wk    = (const float*)d_in[9];
    const float* Wv    = (const float*)d_in[10];
    const float* Wg    = (const float*)d_in[11];
    const float* bg    = (const float*)d_in[12];
    const float* Wo    = (const float*)d_in[13];
    const float* bo    = (const float*)d_in[14];
    float* out = (float*)d_out;

    cudaStream_t s1;
    cudaEvent_t eFork, eJoin;
    cudaStreamCreateWithFlags(&s1, cudaStreamNonBlocking);
    cudaEventCreateWithFlags(&eFork, cudaEventDisableTiming);
    cudaEventCreateWithFlags(&eJoin, cudaEventDisableTiming);

    cudaEventRecord(eFork, 0);
    cudaStreamWaitEvent(s1, eFork, 0);

    k_prep<<<1, 128, 0, s1>>>(lnzw, lnzb, Wz);          // launch 0
    k_bias<<<dim3(6, 768), 128, 0, s1>>>(z);            // launch 1
    cudaEventRecord(eJoin, s1);

    k_proj<<<dim3(6, 12, 4), 256>>>(a, lnaw, lnab, Wq, Wk, Wv, Wg, bg);  // launch 2

    cudaStreamWaitEvent(0, eJoin, 0);
    k_attn<<<dim3(48, 16), 256>>>(mask);                // launch 3 (profiled)
    k_oproj<<<dim3(6, 12), 128>>>(Wo, bo, out);         // launch 4
}

// round 8
// speedup vs baseline: 1.1506x; 1.1506x over previous
#include <cuda_runtime.h>
#include <cuda_fp16.h>

#define NN 768
#define CC 384
#define CZd 128
#define HHd 16
#define CHD 24
#define NP (NN*NN)
#define INFV 1e9f
#define EPSV 1e-5f

typedef unsigned long long u64;
typedef unsigned int u32;

// ------------------------- device scratch (no runtime alloc) ----------------
__device__ float g_an[NN*CC];
__device__ float g_q[NN*CC];
__device__ float g_k[NN*CC];
__device__ float g_v[NN*CC];
__device__ float g_g[NN*CC];
__device__ float g_o[NN*CC];
__device__ float g_Wpp[2048];          // packed [c2][h][2] : {Wp[2c][h], Wp[2c+1][h]}
__device__ float g_S[HHd];
__device__ float g_Cb[HHd];
__device__ __half g_bias[(size_t)HHd*NP];   // [h][i*768 + j]

// ------------------------- packed f32x2 helpers (sm_103a) -------------------
__device__ __forceinline__ u64 pk2(float x, float y){
    u64 r; asm("mov.b64 %0,{%1,%2};" : "=l"(r) : "r"(__float_as_uint(x)), "r"(__float_as_uint(y))); return r;
}
__device__ __forceinline__ float2 up2(u64 v){
    u32 a,b; asm("mov.b64 {%0,%1},%2;" : "=r"(a), "=r"(b) : "l"(v));
    return make_float2(__uint_as_float(a), __uint_as_float(b));
}
__device__ __forceinline__ u64 ffma2(u64 a, u64 b, u64 c){
    u64 d; asm("fma.rn.f32x2 %0,%1,%2,%3;" : "=l"(d) : "l"(a), "l"(b), "l"(c)); return d;
}
__device__ __forceinline__ u64 fmul2(u64 a, u64 b){
    u64 d; asm("mul.rn.f32x2 %0,%1,%2;" : "=l"(d) : "l"(a), "l"(b)); return d;
}
__device__ __forceinline__ u64 fadd2(u64 a, u64 b){
    u64 d; asm("add.rn.f32x2 %0,%1,%2;" : "=l"(d) : "l"(a), "l"(b)); return d;
}
__device__ __forceinline__ float sigmoidf_(float x){ return 1.f/(1.f + __expf(-x)); }

// ------------------------- kernel 1: fold LN(z) weights ---------------------
__global__ void k_prep(const float* __restrict__ lnzw, const float* __restrict__ lnzb,
                       const float* __restrict__ Wz){
    __shared__ float sw[128][17];
    __shared__ float sb[128][17];
    int c = threadIdx.x;   // 0..127
    float w = lnzw[c], b = lnzb[c];
    #pragma unroll
    for(int h=0; h<16; h++){
        float wz = Wz[c*16 + h];
        float wp = w*wz;
        sw[c][h] = wp;
        sb[c][h] = b*wz;
        g_Wpp[(c>>1)*32 + h*2 + (c&1)] = wp;
    }
    __syncthreads();
    if(c < 16){
        float s = 0.f, cb = 0.f;
        for(int j=0; j<128; j++){ s += sw[j][c]; cb += sb[j][c]; }
        g_S[c] = s; g_Cb[c] = cb;
    }
}

// ------------------------- kernel 2: LayerNorm(a) ---------------------------
__global__ void k_lna(const float* __restrict__ a, const float* __restrict__ w,
                      const float* __restrict__ b){
    int warp = threadIdx.x >> 5, lane = threadIdx.x & 31;
    int row = blockIdx.x*8 + warp;
    const float* ar = a + (size_t)row*CC;
    float v[12]; float s = 0.f, ss = 0.f;
    #pragma unroll
    for(int r=0; r<12; r++){ v[r] = ar[lane + r*32]; s += v[r]; ss += v[r]*v[r]; }
    #pragma unroll
    for(int o=16; o; o>>=1){ s += __shfl_xor_sync(~0u, s, o); ss += __shfl_xor_sync(~0u, ss, o); }
    float mu = s * (1.f/CC);
    float rs = rsqrtf(ss*(1.f/CC) - mu*mu + EPSV);
    float* dr = g_an + (size_t)row*CC;
    #pragma unroll
    for(int r=0; r<12; r++){
        int cc = lane + r*32;
        dr[cc] = (v[r]-mu)*rs*w[cc] + b[cc];
    }
}

// ------------------------- kernel 3: QKVG projections (measured 30us) -------
// grid (6, 12, 4), 128 threads. C[m][n] = an @ W, +bg for z==3.
__global__ void __launch_bounds__(128) k_proj(const float* __restrict__ Wq,
                                              const float* __restrict__ Wk2,
                                              const float* __restrict__ Wv2,
                                              const float* __restrict__ Wg2,
                                              const float* __restrict__ bg){
    __shared__ __align__(16) float As[64*36];
    __shared__ __align__(16) float Bs[32*68];
    int t = threadIdx.x;
    int n0 = blockIdx.x*64, m0 = blockIdx.y*64, zz = blockIdx.z;
    const float* W = (zz==0) ? Wq : (zz==1) ? Wk2 : (zz==2) ? Wv2 : Wg2;
    float* Cd = (zz==0) ? g_q : (zz==1) ? g_k : (zz==2) ? g_v : g_g;
    u64 acc[4][4];
    #pragma unroll
    for(int r=0;r<4;r++){ acc[r][0]=0; acc[r][1]=0; acc[r][2]=0; acc[r][3]=0; }
    int tm = t & 15, tn = t >> 4;

    for(int k0=0; k0<CC; k0+=32){
        __syncthreads();
        #pragma unroll
        for(int r=0; r<4; r++){
            int idx = t + 128*r;
            int row = idx >> 3, c4 = idx & 7;
            float4 av = *(const float4*)&g_an[(size_t)(m0+row)*CC + k0 + c4*4];
            *(float4*)&As[row*36 + c4*4] = av;
            int kr = idx >> 4, n4 = idx & 15;
            float4 bv = *(const float4*)&W[(size_t)(k0+kr)*CC + n0 + n4*4];
            *(float4*)&Bs[kr*68 + n4*4] = bv;
        }
        __syncthreads();
        #pragma unroll 8
        for(int kk=0; kk<32; kk++){
            u64 b0 = *(const u64*)&Bs[kk*68 + tn*8 + 0];
            u64 b1 = *(const u64*)&Bs[kk*68 + tn*8 + 2];
            u64 b2 = *(const u64*)&Bs[kk*68 + tn*8 + 4];
            u64 b3 = *(const u64*)&Bs[kk*68 + tn*8 + 6];
            #pragma unroll
            for(int r=0; r<4; r++){
                float a = As[(tm + 16*r)*36 + kk];
                u64 a2 = pk2(a, a);
                acc[r][0] = ffma2(a2, b0, acc[r][0]);
                acc[r][1] = ffma2(a2, b1, acc[r][1]);
                acc[r][2] = ffma2(a2, b2, acc[r][2]);
                acc[r][3] = ffma2(a2, b3, acc[r][3]);
            }
        }
    }
    #pragma unroll
    for(int r=0; r<4; r++){
        int m = m0 + tm + 16*r;
        #pragma unroll
        for(int p=0; p<4; p++){
            int n = n0 + tn*8 + 2*p;
            float2 vv = up2(acc[r][p]);
            if(zz == 3){ vv.x += bg[n]; vv.y += bg[n+1]; }
            *(float2*)&Cd[(size_t)m*CC + n] = vv;
        }
    }
}

// ------------------------- kernel 4: pair bias (measured 98us) --------------
// grid (6, 768): blockIdx.y = i, blockIdx.x = j-tile of 128. 128 threads.
__global__ void __launch_bounds__(128) k_bias(const float* __restrict__ z){
    __shared__ __align__(16) float zs[128*68];    // 128 j rows x 64 c (per phase), pad 68
    __shared__ __align__(16) float swp[2048];     // packed Wp
    __shared__ float smu[128], srs[128];
    __shared__ float sS[16], sCb[16];
    int t = threadIdx.x;
    int i  = blockIdx.y;
    int j0 = blockIdx.x*128;
    #pragma unroll
    for(int r=0; r<16; r++) swp[r*128 + t] = g_Wpp[r*128 + t];

    const float* zbase = z + ((size_t)i*NN + j0)*CZd;
    float sum = 0.f, ssq = 0.f;
    u64 acc[16];
    #pragma unroll
    for(int q=0; q<16; q++) acc[q] = 0ull;
    int hg = t & 3, jg = t >> 2;

    #pragma unroll
    for(int p=0; p<2; p++){
        __syncthreads();
        // cooperative coalesced load of 128 j x 64 c (half of CZ)
        #pragma unroll
        for(int r=0; r<16; r++){
            int idx = t + 128*r;
            int j = idx >> 4, c4 = idx & 15;
            float4 zv = *(const float4*)(zbase + (size_t)j*CZd + p*64 + c4*4);
            *(float4*)&zs[j*68 + c4*4] = zv;
        }
        __syncthreads();
        // stats for j = t
        #pragma unroll
        for(int c2=0; c2<32; c2++){
            float2 zz = up2(*(const u64*)&zs[t*68 + 2*c2]);
            sum += zz.x + zz.y;
            ssq = fmaf(zz.x, zz.x, ssq); ssq = fmaf(zz.y, zz.y, ssq);
        }
        // dots: 4 j (stride 32) x 4 h per thread
        const float* wbase = swp + p*32*32 + hg*8;
        #pragma unroll 4
        for(int c2=0; c2<32; c2++){
            const u64* wr = (const u64*)(wbase + c2*32);
            u64 w0 = wr[0], w1 = wr[1], w2 = wr[2], w3 = wr[3];
            #pragma unroll
            for(int s4=0; s4<4; s4++){
                u64 zv = *(const u64*)&zs[(jg + 32*s4)*68 + 2*c2];
                acc[s4*4+0] = ffma2(zv, w0, acc[s4*4+0]);
                acc[s4*4+1] = ffma2(zv, w1, acc[s4*4+1]);
                acc[s4*4+2] = ffma2(zv, w2, acc[s4*4+2]);
                acc[s4*4+3] = ffma2(zv, w3, acc[s4*4+3]);
            }
        }
    }
    float mu = sum * (1.f/128.f);
    float rs = rsqrtf(ssq*(1.f/128.f) - mu*mu + EPSV);
    smu[t] = mu; srs[t] = rs;
    if(t < 16){ sS[t] = g_S[t]; sCb[t] = g_Cb[t]; }
    __syncthreads();

    // finalize into half staging (reuse zs memory)
    __half* sh = (__half*)zs;
    #pragma unroll
    for(int s4=0; s4<4; s4++){
        int j = jg + 32*s4;
        float m_ = smu[j], r_ = srs[j];
        #pragma unroll
        for(int hi=0; hi<4; hi++){
            int h = hg*4 + hi;
            float2 d = up2(acc[s4*4+hi]);
            float bv = r_*((d.x + d.y) - m_*sS[h]) + sCb[h];
            sh[h*128 + j] = __float2half(bv);
        }
    }
    __syncthreads();
    const u32* sh2 = (const u32*)sh;
    #pragma unroll
    for(int r=0; r<8; r++){
        int lin = r*128 + t;
        int h = lin >> 6, j2 = lin & 63;
        *(u32*)&g_bias[(size_t)h*NP + (size_t)i*NN + j0 + j2*2] = sh2[h*64 + j2];
    }
}

// ------------------------- kernel 5: attention (measured 91.5us) ------------
// grid (24, 16): blockIdx.x = q-tile of 32, blockIdx.y = h. 256 threads.
// Tile-batched scores for ILP: 8 independent dots, one max update per tile.
__global__ void __launch_bounds__(256) k_attn(const float* __restrict__ mask){
    __shared__ __align__(16) float qs[32*26];
    __shared__ __align__(16) float ks[64*26];
    __shared__ __align__(16) float vs[64*26];
    __shared__ float sbf[32*64];
    __shared__ float smb[NN];
    int t = threadIdx.x;
    int h = blockIdx.y, q0 = blockIdx.x*32;
    const float scale = 0.20412414523193154f;  // 24^-0.5

    for(int idx=t; idx<32*24; idx+=256){
        int qq = idx/24, c = idx - qq*24;
        qs[qq*26 + c] = g_q[(size_t)(q0+qq)*CC + h*CHD + c] * scale;
    }
    for(int idx=t; idx<NN; idx+=256) smb[idx] = INFV*(mask[idx] - 1.f);
    __syncthreads();

    int qq = t >> 3, k8 = t & 7;
    u64 qv[12];
    #pragma unroll
    for(int i2=0; i2<12; i2++) qv[i2] = *(const u64*)&qs[qq*26 + 2*i2];

    float mx = -1e30f, l = 0.f;
    u64 acc[12];
    #pragma unroll
    for(int i2=0; i2<12; i2++) acc[i2] = 0ull;
    const size_t hNP = (size_t)h*NP;

    for(int kt=0; kt<NN; kt+=64){
        __syncthreads();
        for(int idx=t; idx<64*24; idx+=256){
            int kk = idx/24, c = idx - kk*24;
            ks[kk*26 + c] = g_k[(size_t)(kt+kk)*CC + h*CHD + c];
            vs[kk*26 + c] = g_v[(size_t)(kt+kk)*CC + h*CHD + c];
        }
        #pragma unroll
        for(int r=0; r<4; r++){
            int idx = t + 256*r;
            int q = idx >> 5, k2 = idx & 31;
            u32 pv = *(const u32*)&g_bias[hNP + (size_t)(q0+q)*NN + kt + 2*k2];
            __half2 hh = *(__half2*)&pv;
            float2 fv = __half22float2(hh);
            sbf[q*64 + 2*k2]     = fv.x + smb[kt + 2*k2];
            sbf[q*64 + 2*k2 + 1] = fv.y + smb[kt + 2*k2 + 1];
        }
        __syncthreads();

        // phase 1: 8 independent score chains
        float sarr[8];
        #pragma unroll
        for(int ii=0; ii<8; ii++){
            int kk = k8 + ii*8;
            u64 d2 = 0ull;
            #pragma unroll
            for(int i2=0; i2<12; i2++) d2 = ffma2(qv[i2], *(const u64*)&ks[kk*26 + 2*i2], d2);
            float2 dd = up2(d2);
            sarr[ii] = dd.x + dd.y + sbf[qq*64 + kk];
        }
        // phase 2: one max update per tile
        float tmax = sarr[0];
        #pragma unroll
        for(int ii=1; ii<8; ii++) tmax = fmaxf(tmax, sarr[ii]);
        if(tmax > mx){
            float f = __expf(mx - tmax);
            l *= f;
            u64 f2 = pk2(f, f);
            #pragma unroll
            for(int i2=0; i2<12; i2++) acc[i2] = fmul2(acc[i2], f2);
            mx = tmax;
        }
        // phase 3: independent exp + PV
        #pragma unroll
        for(int ii=0; ii<8; ii++){
            int kk = k8 + ii*8;
            float e = __expf(sarr[ii] - mx);
            l += e;
            u64 e2 = pk2(e, e);
            #pragma unroll
            for(int i2=0; i2<12; i2++) acc[i2] = ffma2(*(const u64*)&vs[kk*26 + 2*i2], e2, acc[i2]);
        }
    }
    // merge the 8 lanes that share a q
    #pragma unroll
    for(int off=1; off<8; off<<=1){
        float om = __shfl_xor_sync(~0u, mx, off);
        float ol = __shfl_xor_sync(~0u, l,  off);
        float nm = fmaxf(mx, om);
        float fs = __expf(mx - nm), fo = __expf(om - nm);
        l = l*fs + ol*fo;
        u64 fs2 = pk2(fs, fs), fo2 = pk2(fo, fo);
        #pragma unroll
        for(int i2=0; i2<12; i2++){
            float2 av = up2(acc[i2]);
            float ox = __shfl_xor_sync(~0u, av.x, off);
            float oy = __shfl_xor_sync(~0u, av.y, off);
            acc[i2] = fadd2(fmul2(acc[i2], fs2), fmul2(pk2(ox, oy), fo2));
        }
        mx = nm;
    }
    if(k8 == 0){
        float inv = 1.f / l;
        u64 iv = pk2(inv, inv);
        float* op = g_o + (size_t)(q0+qq)*CC + h*CHD;
        #pragma unroll
        for(int i2=0; i2<12; i2++){
            float2 vv = up2(fmul2(acc[i2], iv));
            *(float2*)&op[2*i2] = vv;
        }
    }
}

// ------------------------- kernel 6: gated output projection ----------------
__global__ void __launch_bounds__(128) k_oproj(const float* __restrict__ Wo,
                                               const float* __restrict__ bo,
                                               float* __restrict__ out){
    __shared__ __align__(16) float As[64*36];
    __shared__ __align__(16) float Bs[32*68];
    int t = threadIdx.x;
    int n0 = blockIdx.x*64, m0 = blockIdx.y*64;
    u64 acc[4][4];
    #pragma unroll
    for(int r=0;r<4;r++){ acc[r][0]=0; acc[r][1]=0; acc[r][2]=0; acc[r][3]=0; }
    int tm = t & 15, tn = t >> 4;

    for(int k0=0; k0<CC; k0+=32){
        __syncthreads();
        #pragma unroll
        for(int r=0; r<4; r++){
            int idx = t + 128*r;
            int row = idx >> 3, c4 = idx & 7;
            size_t aoff = (size_t)(m0+row)*CC + k0 + c4*4;
            float4 ov = *(const float4*)&g_o[aoff];
            float4 gv = *(const float4*)&g_g[aoff];
            float4 av;
            av.x = ov.x * sigmoidf_(gv.x);
            av.y = ov.y * sigmoidf_(gv.y);
            av.z = ov.z * sigmoidf_(gv.z);
            av.w = ov.w * sigmoidf_(gv.w);
            *(float4*)&As[row*36 + c4*4] = av;
            int kr = idx >> 4, n4 = idx & 15;
            float4 bv = *(const float4*)&Wo[(size_t)(k0+kr)*CC + n0 + n4*4];
            *(float4*)&Bs[kr*68 + n4*4] = bv;
        }
        __syncthreads();
        #pragma unroll 8
        for(int kk=0; kk<32; kk++){
            u64 b0 = *(const u64*)&Bs[kk*68 + tn*8 + 0];
            u64 b1 = *(const u64*)&Bs[kk*68 + tn*8 + 2];
            u64 b2 = *(const u64*)&Bs[kk*68 + tn*8 + 4];
            u64 b3 = *(const u64*)&Bs[kk*68 + tn*8 + 6];
            #pragma unroll
            for(int r=0; r<4; r++){
                float av = As[(tm + 16*r)*36 + kk];
                u64 a2 = pk2(av, av);
                acc[r][0] = ffma2(a2, b0, acc[r][0]);
                acc[r][1] = ffma2(a2, b1, acc[r][1]);
                acc[r][2] = ffma2(a2, b2, acc[r][2]);
                acc[r][3] = ffma2(a2, b3, acc[r][3]);
            }
        }
    }
    #pragma unroll
    for(int r=0; r<4; r++){
        int m = m0 + tm + 16*r;
        #pragma unroll
        for(int p=0; p<4; p++){
            int n = n0 + tn*8 + 2*p;
            float2 vv = up2(acc[r][p]);
            vv.x += bo[n]; vv.y += bo[n+1];
            *(float2*)&out[(size_t)m*CC + n] = vv;
        }
    }
}

// ------------------------- launch (serial; bias at profiled idx 3) ----------
extern "C" void kernel_launch(void* const* d_in, const int* in_sizes, int n_in,
                              void* d_out, int out_size){
    const float* a     = (const float*)d_in[0];
    const float* z     = (const float*)d_in[1];
    const float* mask  = (const float*)d_in[2];
    const float* lnaw  = (const float*)d_in[3];
    const float* lnab  = (const float*)d_in[4];
    const float* lnzw  = (const float*)d_in[5];
    const float* lnzb  = (const float*)d_in[6];
    const float* Wz    = (const float*)d_in[7];
    const float* Wq    = (const float*)d_in[8];
    const float* Wk    = (const float*)d_in[9];
    const float* Wv    = (const float*)d_in[10];
    const float* Wg    = (const float*)d_in[11];
    const float* bg    = (const float*)d_in[12];
    const float* Wo    = (const float*)d_in[13];
    const float* bo    = (const float*)d_in[14];
    float* out = (float*)d_out;

    k_prep<<<1, 128>>>(lnzw, lnzb, Wz);                                  // 0
    k_lna<<<96, 256>>>(a, lnaw, lnab);                                   // 1
    k_proj<<<dim3(6, 12, 4), 128>>>(Wq, Wk, Wv, Wg, bg);                 // 2
    k_bias<<<dim3(6, 768), 128>>>(z);                                    // 3 (profiled)
    k_attn<<<dim3(24, 16), 256>>>(mask);                                 // 4
    k_oproj<<<dim3(6, 12), 128>>>(Wo, bo, out);                          // 5
}

// round 10
// speedup vs baseline: 1.2687x; 1.1027x over previous
#include <cuda_runtime.h>
#include <cuda_fp16.h>

#define NN 768
#define CC 384
#define CZd 128
#define HHd 16
#define CHD 24
#define NP (NN*NN)
#define INFV 1e9f
#define EPSV 1e-5f

typedef unsigned long long u64;
typedef unsigned int u32;

// ------------------------- device scratch (no runtime alloc) ----------------
__device__ float g_an[NN*CC];
__device__ float g_q[NN*CC];
__device__ float g_k[NN*CC];
__device__ float g_v[NN*CC];
__device__ float g_g[NN*CC];
__device__ float g_o[NN*CC];
__device__ float g_Wpt[16*128];        // tf32-rounded Wp^T : [h][c]
__device__ float g_S[HHd];
__device__ float g_Cb[HHd];
__device__ __half g_bias[(size_t)HHd*NP];   // [h][i*768 + j]

// ------------------------- packed f32x2 helpers (sm_103a) -------------------
__device__ __forceinline__ u64 pk2(float x, float y){
    u64 r; asm("mov.b64 %0,{%1,%2};" : "=l"(r) : "r"(__float_as_uint(x)), "r"(__float_as_uint(y))); return r;
}
__device__ __forceinline__ float2 up2(u64 v){
    u32 a,b; asm("mov.b64 {%0,%1},%2;" : "=r"(a), "=r"(b) : "l"(v));
    return make_float2(__uint_as_float(a), __uint_as_float(b));
}
__device__ __forceinline__ u64 ffma2(u64 a, u64 b, u64 c){
    u64 d; asm("fma.rn.f32x2 %0,%1,%2,%3;" : "=l"(d) : "l"(a), "l"(b), "l"(c)); return d;
}
__device__ __forceinline__ u64 fmul2(u64 a, u64 b){
    u64 d; asm("mul.rn.f32x2 %0,%1,%2;" : "=l"(d) : "l"(a), "l"(b)); return d;
}
__device__ __forceinline__ u64 fadd2(u64 a, u64 b){
    u64 d; asm("add.rn.f32x2 %0,%1,%2;" : "=l"(d) : "l"(a), "l"(b)); return d;
}
__device__ __forceinline__ float sigmoidf_(float x){ return 1.f/(1.f + __expf(-x)); }

// ------------------------- tf32 warp mma (baseline PTX, sm_103-legal) -------
__device__ __forceinline__ void mma_tf32(float* d, u32 a0, u32 a1, u32 a2, u32 a3,
                                         u32 b0, u32 b1){
    asm volatile(
        "mma.sync.aligned.m16n8k8.row.col.f32.tf32.tf32.f32 "
        "{%0,%1,%2,%3}, {%4,%5,%6,%7}, {%8,%9}, {%0,%1,%2,%3};"
        : "+f"(d[0]), "+f"(d[1]), "+f"(d[2]), "+f"(d[3])
        : "r"(a0), "r"(a1), "r"(a2), "r"(a3), "r"(b0), "r"(b1));
}

// ------------------------- kernel 1: fold LN(z) weights ---------------------
__global__ void k_prep(const float* __restrict__ lnzw, const float* __restrict__ lnzb,
                       const float* __restrict__ Wz){
    __shared__ float sw[128][17];
    __shared__ float sb[128][17];
    int c = threadIdx.x;   // 0..127
    float w = lnzw[c], b = lnzb[c];
    #pragma unroll
    for(int h=0; h<16; h++){
        float wz = Wz[c*16 + h];
        float wp = w*wz;
        u32 tf; asm("cvt.rna.tf32.f32 %0, %1;" : "=r"(tf) : "f"(wp));
        float wpr = __uint_as_float(tf);
        g_Wpt[h*128 + c] = wpr;
        sw[c][h] = wpr;              // S uses the rounded weights (consistency)
        sb[c][h] = b*wz;
    }
    __syncthreads();
    if(c < 16){
        float s = 0.f, cb = 0.f;
        for(int j=0; j<128; j++){ s += sw[j][c]; cb += sb[j][c]; }
        g_S[c] = s; g_Cb[c] = cb;
    }
}

// ------------------------- kernel 2: LayerNorm(a) ---------------------------
__global__ void k_lna(const float* __restrict__ a, const float* __restrict__ w,
                      const float* __restrict__ b){
    int warp = threadIdx.x >> 5, lane = threadIdx.x & 31;
    int row = blockIdx.x*8 + warp;
    const float* ar = a + (size_t)row*CC;
    float v[12]; float s = 0.f, ss = 0.f;
    #pragma unroll
    for(int r=0; r<12; r++){ v[r] = ar[lane + r*32]; s += v[r]; ss += v[r]*v[r]; }
    #pragma unroll
    for(int o=16; o; o>>=1){ s += __shfl_xor_sync(~0u, s, o); ss += __shfl_xor_sync(~0u, ss, o); }
    float mu = s * (1.f/CC);
    float rs = rsqrtf(ss*(1.f/CC) - mu*mu + EPSV);
    float* dr = g_an + (size_t)row*CC;
    #pragma unroll
    for(int r=0; r<12; r++){
        int cc = lane + r*32;
        dr[cc] = (v[r]-mu)*rs*w[cc] + b[cc];
    }
}

// ------------------------- kernel 3: QKVG projections -----------------------
__global__ void __launch_bounds__(128) k_proj(const float* __restrict__ Wq,
                                              const float* __restrict__ Wk2,
                                              const float* __restrict__ Wv2,
                                              const float* __restrict__ Wg2,
                                              const float* __restrict__ bg){
    __shared__ __align__(16) float As[64*36];
    __shared__ __align__(16) float Bs[32*68];
    int t = threadIdx.x;
    int n0 = blockIdx.x*64, m0 = blockIdx.y*64, zz = blockIdx.z;
    const float* W = (zz==0) ? Wq : (zz==1) ? Wk2 : (zz==2) ? Wv2 : Wg2;
    float* Cd = (zz==0) ? g_q : (zz==1) ? g_k : (zz==2) ? g_v : g_g;
    u64 acc[4][4];
    #pragma unroll
    for(int r=0;r<4;r++){ acc[r][0]=0; acc[r][1]=0; acc[r][2]=0; acc[r][3]=0; }
    int tm = t & 15, tn = t >> 4;

    for(int k0=0; k0<CC; k0+=32){
        __syncthreads();
        #pragma unroll
        for(int r=0; r<4; r++){
            int idx = t + 128*r;
            int row = idx >> 3, c4 = idx & 7;
            float4 av = *(const float4*)&g_an[(size_t)(m0+row)*CC + k0 + c4*4];
            *(float4*)&As[row*36 + c4*4] = av;
            int kr = idx >> 4, n4 = idx & 15;
            float4 bv = *(const float4*)&W[(size_t)(k0+kr)*CC + n0 + n4*4];
            *(float4*)&Bs[kr*68 + n4*4] = bv;
        }
        __syncthreads();
        #pragma unroll 8
        for(int kk=0; kk<32; kk++){
            u64 b0 = *(const u64*)&Bs[kk*68 + tn*8 + 0];
            u64 b1 = *(const u64*)&Bs[kk*68 + tn*8 + 2];
            u64 b2 = *(const u64*)&Bs[kk*68 + tn*8 + 4];
            u64 b3 = *(const u64*)&Bs[kk*68 + tn*8 + 6];
            #pragma unroll
            for(int r=0; r<4; r++){
                float a = As[(tm + 16*r)*36 + kk];
                u64 a2 = pk2(a, a);
                acc[r][0] = ffma2(a2, b0, acc[r][0]);
                acc[r][1] = ffma2(a2, b1, acc[r][1]);
                acc[r][2] = ffma2(a2, b2, acc[r][2]);
                acc[r][3] = ffma2(a2, b3, acc[r][3]);
            }
        }
    }
    #pragma unroll
    for(int r=0; r<4; r++){
        int m = m0 + tm + 16*r;
        #pragma unroll
        for(int p=0; p<4; p++){
            int n = n0 + tn*8 + 2*p;
            float2 vv = up2(acc[r][p]);
            if(zz == 3){ vv.x += bg[n]; vv.y += bg[n+1]; }
            *(float2*)&Cd[(size_t)m*CC + n] = vv;
        }
    }
}

// ------------------------- kernel 4: pair bias via mma.sync tf32 ------------
// grid (6, 768): blockIdx.y = i, blockIdx.x = j-tile of 128. 128 threads.
// Two-phase staging (64 c per phase); warp w owns rows [32w, 32w+32):
// per phase 8 k-tiles x 2 m-tiles x 2 n-tiles of m16n8k8 tf32 mma.
// Stats fused (row t swept once from smem); all LDS conflict-free.
__global__ void __launch_bounds__(128) k_bias(const float* __restrict__ z){
    __shared__ __align__(16) float wt[16*132];     // 8.4KB  [h][c] tf32 weights
    __shared__ __align__(16) float zs[128*68];     // 34.8KB z phase tile / half staging
    __shared__ float smu[128], srs[128], sS[16], sCb[16];
    int t = threadIdx.x;
    int warp = t >> 5, lane = t & 31, g = lane >> 2, tig = lane & 3;
    int i = blockIdx.y, j0 = blockIdx.x*128;

    // stage weights [16][132]
    #pragma unroll
    for(int r=0; r<4; r++){
        int idx = t + 128*r;             // 512 float4s = 2048 floats
        int h = idx >> 5, cq = idx & 31;
        *(float4*)&wt[h*132 + cq*4] = *(const float4*)&g_Wpt[h*128 + cq*4];
    }
    if(t < 16){ sS[t] = g_S[t]; sCb[t] = g_Cb[t]; }

    const float* zbase = z + ((size_t)i*NN + j0)*CZd;
    float sum = 0.f, ssq = 0.f;
    float d[2][2][4] = {};               // [m-tile][n-tile][frag]

    #pragma unroll
    for(int p=0; p<2; p++){
        __syncthreads();
        // stage 128 j x 64 c
        #pragma unroll
        for(int r=0; r<16; r++){
            int idx = t + 128*r;
            int j = idx >> 4, cq = idx & 15;
            *(float4*)&zs[j*68 + cq*4] =
                *(const float4*)(zbase + (size_t)j*CZd + p*64 + cq*4);
        }
        __syncthreads();
        // stats for row t (fused; conflict-free float4 sweep)
        #pragma unroll
        for(int c=0; c<16; c++){
            float4 v = *(const float4*)&zs[t*68 + c*4];
            sum += (v.x + v.y) + (v.z + v.w);
            ssq = fmaf(v.x, v.x, ssq); ssq = fmaf(v.y, v.y, ssq);
            ssq = fmaf(v.z, v.z, ssq); ssq = fmaf(v.w, v.w, ssq);
        }
        // tensor-core dots
        #pragma unroll
        for(int kt=0; kt<8; kt++){
            int kb = kt*8;
            int kw = p*64 + kb;
            u32 b00 = *(const u32*)&wt[g*132       + kw + tig];
            u32 b01 = *(const u32*)&wt[g*132       + kw + tig + 4];
            u32 b10 = *(const u32*)&wt[(8+g)*132   + kw + tig];
            u32 b11 = *(const u32*)&wt[(8+g)*132   + kw + tig + 4];
            #pragma unroll
            for(int mt=0; mt<2; mt++){
                int rb = warp*32 + mt*16;
                u32 a0 = *(const u32*)&zs[(rb+g)*68   + kb + tig];
                u32 a1 = *(const u32*)&zs[(rb+g+8)*68 + kb + tig];
                u32 a2 = *(const u32*)&zs[(rb+g)*68   + kb + tig + 4];
                u32 a3 = *(const u32*)&zs[(rb+g+8)*68 + kb + tig + 4];
                mma_tf32(d[mt][0], a0, a1, a2, a3, b00, b01);
                mma_tf32(d[mt][1], a0, a1, a2, a3, b10, b11);
            }
        }
    }
    float mu = sum * (1.f/128.f);
    float rs = rsqrtf(ssq*(1.f/128.f) - mu*mu + EPSV);
    smu[t] = mu; srs[t] = rs;
    __syncthreads();                     // stats visible; zs free for reuse

    // epilogue: LN finalize + fp16 staging (reuse zs)
    __half* sh = (__half*)zs;            // [h][128 j]
    #pragma unroll
    for(int mt=0; mt<2; mt++){
        int rA = warp*32 + mt*16 + g;
        int rB = rA + 8;
        float muA = smu[rA], rsA = srs[rA];
        float muB = smu[rB], rsB = srs[rB];
        #pragma unroll
        for(int nt=0; nt<2; nt++){
            int h0 = nt*8 + 2*tig, h1 = h0 + 1;
            sh[h0*128 + rA] = __float2half(rsA*(d[mt][nt][0] - muA*sS[h0]) + sCb[h0]);
            sh[h1*128 + rA] = __float2half(rsA*(d[mt][nt][1] - muA*sS[h1]) + sCb[h1]);
            sh[h0*128 + rB] = __float2half(rsB*(d[mt][nt][2] - muB*sS[h0]) + sCb[h0]);
            sh[h1*128 + rB] = __float2half(rsB*(d[mt][nt][3] - muB*sS[h1]) + sCb[h1]);
        }
    }
    __syncthreads();
    const u32* shp = (const u32*)sh;
    #pragma unroll
    for(int r=0; r<8; r++){
        int lin = r*128 + t;
        int h = lin >> 6, j2 = lin & 63;
        *(u32*)&g_bias[(size_t)h*NP + (size_t)i*NN + j0 + 2*j2] = shp[h*64 + j2];
    }
}

// ------------------------- kernel 5: attention (measured 91.5us cfg) --------
__global__ void __launch_bounds__(256) k_attn(const float* __restrict__ mask){
    __shared__ __align__(16) float qs[32*26];
    __shared__ __align__(16) float ks[64*26];
    __shared__ __align__(16) float vs[64*26];
    __shared__ float sbf[32*64];
    __shared__ float smb[NN];
    int t = threadIdx.x;
    int h = blockIdx.y, q0 = blockIdx.x*32;
    const float scale = 0.20412414523193154f;  // 24^-0.5

    for(int idx=t; idx<32*24; idx+=256){
        int qq = idx/24, c = idx - qq*24;
        qs[qq*26 + c] = g_q[(size_t)(q0+qq)*CC + h*CHD + c] * scale;
    }
    for(int idx=t; idx<NN; idx+=256) smb[idx] = INFV*(mask[idx] - 1.f);
    __syncthreads();

    int qq = t >> 3, k8 = t & 7;
    u64 qv[12];
    #pragma unroll
    for(int i2=0; i2<12; i2++) qv[i2] = *(const u64*)&qs[qq*26 + 2*i2];

    float mx = -1e30f, l = 0.f;
    u64 acc[12];
    #pragma unroll
    for(int i2=0; i2<12; i2++) acc[i2] = 0ull;
    const size_t hNP = (size_t)h*NP;

    for(int kt=0; kt<NN; kt+=64){
        __syncthreads();
        for(int idx=t; idx<64*24; idx+=256){
            int kk = idx/24, c = idx - kk*24;
            ks[kk*26 + c] = g_k[(size_t)(kt+kk)*CC + h*CHD + c];
            vs[kk*26 + c] = g_v[(size_t)(kt+kk)*CC + h*CHD + c];
        }
        #pragma unroll
        for(int r=0; r<4; r++){
            int idx = t + 256*r;
            int q = idx >> 5, k2 = idx & 31;
            u32 pv = *(const u32*)&g_bias[hNP + (size_t)(q0+q)*NN + kt + 2*k2];
            __half2 hh = *(__half2*)&pv;
            float2 fv = __half22float2(hh);
            sbf[q*64 + 2*k2]     = fv.x + smb[kt + 2*k2];
            sbf[q*64 + 2*k2 + 1] = fv.y + smb[kt + 2*k2 + 1];
        }
        __syncthreads();

        float sarr[8];
        #pragma unroll
        for(int ii=0; ii<8; ii++){
            int kk = k8 + ii*8;
            u64 d2 = 0ull;
            #pragma unroll
            for(int i2=0; i2<12; i2++) d2 = ffma2(qv[i2], *(const u64*)&ks[kk*26 + 2*i2], d2);
            float2 dd = up2(d2);
            sarr[ii] = dd.x + dd.y + sbf[qq*64 + kk];
        }
        float tmax = sarr[0];
        #pragma unroll
        for(int ii=1; ii<8; ii++) tmax = fmaxf(tmax, sarr[ii]);
        if(tmax > mx){
            float f = __expf(mx - tmax);
            l *= f;
            u64 f2 = pk2(f, f);
            #pragma unroll
            for(int i2=0; i2<12; i2++) acc[i2] = fmul2(acc[i2], f2);
            mx = tmax;
        }
        #pragma unroll
        for(int ii=0; ii<8; ii++){
            int kk = k8 + ii*8;
            float e = __expf(sarr[ii] - mx);
            l += e;
            u64 e2 = pk2(e, e);
            #pragma unroll
            for(int i2=0; i2<12; i2++) acc[i2] = ffma2(*(const u64*)&vs[kk*26 + 2*i2], e2, acc[i2]);
        }
    }
    #pragma unroll
    for(int off=1; off<8; off<<=1){
        float om = __shfl_xor_sync(~0u, mx, off);
        float ol = __shfl_xor_sync(~0u, l,  off);
        float nm = fmaxf(mx, om);
        float fs = __expf(mx - nm), fo = __expf(om - nm);
        l = l*fs + ol*fo;
        u64 fs2 = pk2(fs, fs), fo2 = pk2(fo, fo);
        #pragma unroll
        for(int i2=0; i2<12; i2++){
            float2 av = up2(acc[i2]);
            float ox = __shfl_xor_sync(~0u, av.x, off);
            float oy = __shfl_xor_sync(~0u, av.y, off);
            acc[i2] = fadd2(fmul2(acc[i2], fs2), fmul2(pk2(ox, oy), fo2));
        }
        mx = nm;
    }
    if(k8 == 0){
        float inv = 1.f / l;
        u64 iv = pk2(inv, inv);
        float* op = g_o + (size_t)(q0+qq)*CC + h*CHD;
        #pragma unroll
        for(int i2=0; i2<12; i2++){
            float2 vv = up2(fmul2(acc[i2], iv));
            *(float2*)&op[2*i2] = vv;
        }
    }
}

// ------------------------- kernel 6: gated output projection ----------------
__global__ void __launch_bounds__(128) k_oproj(const float* __restrict__ Wo,
                                               const float* __restrict__ bo,
                                               float* __restrict__ out){
    __shared__ __align__(16) float As[64*36];
    __shared__ __align__(16) float Bs[32*68];
    int t = threadIdx.x;
    int n0 = blockIdx.x*64, m0 = blockIdx.y*64;
    u64 acc[4][4];
    #pragma unroll
    for(int r=0;r<4;r++){ acc[r][0]=0; acc[r][1]=0; acc[r][2]=0; acc[r][3]=0; }
    int tm = t & 15, tn = t >> 4;

    for(int k0=0; k0<CC; k0+=32){
        __syncthreads();
        #pragma unroll
        for(int r=0; r<4; r++){
            int idx = t + 128*r;
            int row = idx >> 3, c4 = idx & 7;
            size_t aoff = (size_t)(m0+row)*CC + k0 + c4*4;
            float4 ov = *(const float4*)&g_o[aoff];
            float4 gv = *(const float4*)&g_g[aoff];
            float4 av;
            av.x = ov.x * sigmoidf_(gv.x);
            av.y = ov.y * sigmoidf_(gv.y);
            av.z = ov.z * sigmoidf_(gv.z);
            av.w = ov.w * sigmoidf_(gv.w);
            *(float4*)&As[row*36 + c4*4] = av;
            int kr = idx >> 4, n4 = idx & 15;
            float4 bv = *(const float4*)&Wo[(size_t)(k0+kr)*CC + n0 + n4*4];
            *(float4*)&Bs[kr*68 + n4*4] = bv;
        }
        __syncthreads();
        #pragma unroll 8
        for(int kk=0; kk<32; kk++){
            u64 b0 = *(const u64*)&Bs[kk*68 + tn*8 + 0];
            u64 b1 = *(const u64*)&Bs[kk*68 + tn*8 + 2];
            u64 b2 = *(const u64*)&Bs[kk*68 + tn*8 + 4];
            u64 b3 = *(const u64*)&Bs[kk*68 + tn*8 + 6];
            #pragma unroll
            for(int r=0; r<4; r++){
                float av = As[(tm + 16*r)*36 + kk];
                u64 a2 = pk2(av, av);
                acc[r][0] = ffma2(a2, b0, acc[r][0]);
                acc[r][1] = ffma2(a2, b1, acc[r][1]);
                acc[r][2] = ffma2(a2, b2, acc[r][2]);
                acc[r][3] = ffma2(a2, b3, acc[r][3]);
            }
        }
    }
    #pragma unroll
    for(int r=0; r<4; r++){
        int m = m0 + tm + 16*r;
        #pragma unroll
        for(int p=0; p<4; p++){
            int n = n0 + tn*8 + 2*p;
            float2 vv = up2(acc[r][p]);
            vv.x += bo[n]; vv.y += bo[n+1];
            *(float2*)&out[(size_t)m*CC + n] = vv;
        }
    }
}

// ------------------------- launch (serial; bias at profiled idx 3) ----------
extern "C" void kernel_launch(void* const* d_in, const int* in_sizes, int n_in,
                              void* d_out, int out_size){
    const float* a     = (const float*)d_in[0];
    const float* z     = (const float*)d_in[1];
    const float* mask  = (const float*)d_in[2];
    const float* lnaw  = (const float*)d_in[3];
    const float* lnab  = (const float*)d_in[4];
    const float* lnzw  = (const float*)d_in[5];
    const float* lnzb  = (const float*)d_in[6];
    const float* Wz    = (const float*)d_in[7];
    const float* Wq    = (const float*)d_in[8];
    const float* Wk    = (const float*)d_in[9];
    const float* Wv    = (const float*)d_in[10];
    const float* Wg    = (const float*)d_in[11];
    const float* bg    = (const float*)d_in[12];
    const float* Wo    = (const float*)d_in[13];
    const float* bo    = (const float*)d_in[14];
    float* out = (float*)d_out;

    k_prep<<<1, 128>>>(lnzw, lnzb, Wz);                                  // 0
    k_lna<<<96, 256>>>(a, lnaw, lnab);                                   // 1
    k_proj<<<dim3(6, 12, 4), 128>>>(Wq, Wk, Wv, Wg, bg);                 // 2
    k_bias<<<dim3(6, 768), 128>>>(z);                                    // 3 (profiled)
    k_attn<<<dim3(24, 16), 256>>>(mask);                                 // 4
    k_oproj<<<dim3(6, 12), 128>>>(Wo, bo, out);                          // 5
}

// round 11
// speedup vs baseline: 1.2985x; 1.0235x over previous
#include <cuda_runtime.h>
#include <cuda_fp16.h>

#define NN 768
#define CC 384
#define CZd 128
#define HHd 16
#define CHD 24
#define NP (NN*NN)
#define INFV 1e9f
#define EPSV 1e-5f

typedef unsigned long long u64;
typedef unsigned int u32;

// ------------------------- device scratch (no runtime alloc) ----------------
__device__ float g_an[NN*CC];
__device__ float g_q[NN*CC];
__device__ float g_k[NN*CC];
__device__ float g_v[NN*CC];
__device__ float g_g[NN*CC];
__device__ float g_o[NN*CC];
__device__ float g_Wpt[16*128];        // tf32-rounded Wp^T : [h][c]
__device__ float g_S[HHd];
__device__ float g_Cb[HHd];
__device__ __half g_bias[(size_t)HHd*NP];   // [h][i*768 + j]

// ------------------------- packed f32x2 helpers (sm_103a) -------------------
__device__ __forceinline__ u64 pk2(float x, float y){
    u64 r; asm("mov.b64 %0,{%1,%2};" : "=l"(r) : "r"(__float_as_uint(x)), "r"(__float_as_uint(y))); return r;
}
__device__ __forceinline__ float2 up2(u64 v){
    u32 a,b; asm("mov.b64 {%0,%1},%2;" : "=r"(a), "=r"(b) : "l"(v));
    return make_float2(__uint_as_float(a), __uint_as_float(b));
}
__device__ __forceinline__ u64 ffma2(u64 a, u64 b, u64 c){
    u64 d; asm("fma.rn.f32x2 %0,%1,%2,%3;" : "=l"(d) : "l"(a), "l"(b), "l"(c)); return d;
}
__device__ __forceinline__ u64 fmul2(u64 a, u64 b){
    u64 d; asm("mul.rn.f32x2 %0,%1,%2;" : "=l"(d) : "l"(a), "l"(b)); return d;
}
__device__ __forceinline__ u64 fadd2(u64 a, u64 b){
    u64 d; asm("add.rn.f32x2 %0,%1,%2;" : "=l"(d) : "l"(a), "l"(b)); return d;
}
__device__ __forceinline__ float sigmoidf_(float x){ return 1.f/(1.f + __expf(-x)); }

// ------------------------- tf32 warp mma (baseline PTX, sm_103-legal) -------
__device__ __forceinline__ void mma_tf32(float* d, u32 a0, u32 a1, u32 a2, u32 a3,
                                         u32 b0, u32 b1){
    asm volatile(
        "mma.sync.aligned.m16n8k8.row.col.f32.tf32.tf32.f32 "
        "{%0,%1,%2,%3}, {%4,%5,%6,%7}, {%8,%9}, {%0,%1,%2,%3};"
        : "+f"(d[0]), "+f"(d[1]), "+f"(d[2]), "+f"(d[3])
        : "r"(a0), "r"(a1), "r"(a2), "r"(a3), "r"(b0), "r"(b1));
}

// ------------------------- kernel 1: fold LN(z) weights ---------------------
__global__ void k_prep(const float* __restrict__ lnzw, const float* __restrict__ lnzb,
                       const float* __restrict__ Wz){
    __shared__ float sw[128][17];
    __shared__ float sb[128][17];
    int c = threadIdx.x;   // 0..127
    float w = lnzw[c], b = lnzb[c];
    #pragma unroll
    for(int h=0; h<16; h++){
        float wz = Wz[c*16 + h];
        float wp = w*wz;
        u32 tf; asm("cvt.rna.tf32.f32 %0, %1;" : "=r"(tf) : "f"(wp));
        float wpr = __uint_as_float(tf);
        g_Wpt[h*128 + c] = wpr;
        sw[c][h] = wpr;              // S uses the rounded weights (consistency)
        sb[c][h] = b*wz;
    }
    __syncthreads();
    if(c < 16){
        float s = 0.f, cb = 0.f;
        for(int j=0; j<128; j++){ s += sw[j][c]; cb += sb[j][c]; }
        g_S[c] = s; g_Cb[c] = cb;
    }
}

// ------------------------- kernel 2: LayerNorm(a) ---------------------------
__global__ void k_lna(const float* __restrict__ a, const float* __restrict__ w,
                      const float* __restrict__ b){
    int warp = threadIdx.x >> 5, lane = threadIdx.x & 31;
    int row = blockIdx.x*8 + warp;
    const float* ar = a + (size_t)row*CC;
    float v[12]; float s = 0.f, ss = 0.f;
    #pragma unroll
    for(int r=0; r<12; r++){ v[r] = ar[lane + r*32]; s += v[r]; ss += v[r]*v[r]; }
    #pragma unroll
    for(int o=16; o; o>>=1){ s += __shfl_xor_sync(~0u, s, o); ss += __shfl_xor_sync(~0u, ss, o); }
    float mu = s * (1.f/CC);
    float rs = rsqrtf(ss*(1.f/CC) - mu*mu + EPSV);
    float* dr = g_an + (size_t)row*CC;
    #pragma unroll
    for(int r=0; r<12; r++){
        int cc = lane + r*32;
        dr[cc] = (v[r]-mu)*rs*w[cc] + b[cc];
    }
}

// ------------------------- kernel 3: QKVG projections -----------------------
__global__ void __launch_bounds__(128) k_proj(const float* __restrict__ Wq,
                                              const float* __restrict__ Wk2,
                                              const float* __restrict__ Wv2,
                                              const float* __restrict__ Wg2,
                                              const float* __restrict__ bg){
    __shared__ __align__(16) float As[64*36];
    __shared__ __align__(16) float Bs[32*68];
    int t = threadIdx.x;
    int n0 = blockIdx.x*64, m0 = blockIdx.y*64, zz = blockIdx.z;
    const float* W = (zz==0) ? Wq : (zz==1) ? Wk2 : (zz==2) ? Wv2 : Wg2;
    float* Cd = (zz==0) ? g_q : (zz==1) ? g_k : (zz==2) ? g_v : g_g;
    u64 acc[4][4];
    #pragma unroll
    for(int r=0;r<4;r++){ acc[r][0]=0; acc[r][1]=0; acc[r][2]=0; acc[r][3]=0; }
    int tm = t & 15, tn = t >> 4;

    for(int k0=0; k0<CC; k0+=32){
        __syncthreads();
        #pragma unroll
        for(int r=0; r<4; r++){
            int idx = t + 128*r;
            int row = idx >> 3, c4 = idx & 7;
            float4 av = *(const float4*)&g_an[(size_t)(m0+row)*CC + k0 + c4*4];
            *(float4*)&As[row*36 + c4*4] = av;
            int kr = idx >> 4, n4 = idx & 15;
            float4 bv = *(const float4*)&W[(size_t)(k0+kr)*CC + n0 + n4*4];
            *(float4*)&Bs[kr*68 + n4*4] = bv;
        }
        __syncthreads();
        #pragma unroll 8
        for(int kk=0; kk<32; kk++){
            u64 b0 = *(const u64*)&Bs[kk*68 + tn*8 + 0];
            u64 b1 = *(const u64*)&Bs[kk*68 + tn*8 + 2];
            u64 b2 = *(const u64*)&Bs[kk*68 + tn*8 + 4];
            u64 b3 = *(const u64*)&Bs[kk*68 + tn*8 + 6];
            #pragma unroll
            for(int r=0; r<4; r++){
                float a = As[(tm + 16*r)*36 + kk];
                u64 a2 = pk2(a, a);
                acc[r][0] = ffma2(a2, b0, acc[r][0]);
                acc[r][1] = ffma2(a2, b1, acc[r][1]);
                acc[r][2] = ffma2(a2, b2, acc[r][2]);
                acc[r][3] = ffma2(a2, b3, acc[r][3]);
            }
        }
    }
    #pragma unroll
    for(int r=0; r<4; r++){
        int m = m0 + tm + 16*r;
        #pragma unroll
        for(int p=0; p<4; p++){
            int n = n0 + tn*8 + 2*p;
            float2 vv = up2(acc[r][p]);
            if(zz == 3){ vv.x += bg[n]; vv.y += bg[n+1]; }
            *(float2*)&Cd[(size_t)m*CC + n] = vv;
        }
    }
}

// ------------------------- kernel 4: pair bias, tf32 mma + double buffer ----
// grid (6, 768): blockIdx.y = i, blockIdx.x = j-tile of 128. 128 threads.
// 4 phases of 32 c, ping-pong buffers: phase p+1 LDGs issue before phase p's
// mma/stats, hiding DRAM latency. Stats fused; all mma frag LDS conflict-free.
__global__ void __launch_bounds__(128) k_bias(const float* __restrict__ z){
    __shared__ __align__(16) float wt[16*132];       // 8.4KB [h][c]
    __shared__ __align__(16) float zs[2][128*36];    // 2 x 18.4KB ping-pong
    __shared__ float smu[128], srs[128], sS[16], sCb[16];
    int t = threadIdx.x;
    int warp = t >> 5, lane = t & 31, g = lane >> 2, tig = lane & 3;
    int i = blockIdx.y, j0 = blockIdx.x*128;

    #pragma unroll
    for(int r=0; r<4; r++){
        int idx = t + 128*r;
        int h = idx >> 5, cq = idx & 31;
        *(float4*)&wt[h*132 + cq*4] = *(const float4*)&g_Wpt[h*128 + cq*4];
    }
    if(t < 16){ sS[t] = g_S[t]; sCb[t] = g_Cb[t]; }

    const float* zbase = z + ((size_t)i*NN + j0)*CZd;
    float sum = 0.f, ssq = 0.f;
    float d[2][2][4] = {};

    // prologue: load phase 0 into buffer 0
    #pragma unroll
    for(int r=0; r<8; r++){
        int idx = t + 128*r;
        int j = idx >> 3, cq = idx & 7;
        *(float4*)&zs[0][j*36 + cq*4] = *(const float4*)(zbase + (size_t)j*CZd + cq*4);
    }
    __syncthreads();

    #pragma unroll
    for(int p=0; p<4; p++){
        // prefetch next phase into the other buffer
        if(p < 3){
            #pragma unroll
            for(int r=0; r<8; r++){
                int idx = t + 128*r;
                int j = idx >> 3, cq = idx & 7;
                *(float4*)&zs[(p+1)&1][j*36 + cq*4] =
                    *(const float4*)(zbase + (size_t)j*CZd + (p+1)*32 + cq*4);
            }
        }
        const float* zb = zs[p&1];
        // stats for row t
        #pragma unroll
        for(int c=0; c<8; c++){
            float4 v = *(const float4*)&zb[t*36 + c*4];
            sum += (v.x + v.y) + (v.z + v.w);
            ssq = fmaf(v.x, v.x, ssq); ssq = fmaf(v.y, v.y, ssq);
            ssq = fmaf(v.z, v.z, ssq); ssq = fmaf(v.w, v.w, ssq);
        }
        // tensor-core dots: 4 k-steps x 2 m x 2 n
        #pragma unroll
        for(int kt=0; kt<4; kt++){
            int kb = kt*8;
            int kw = p*32 + kb;
            u32 b00 = *(const u32*)&wt[g*132     + kw + tig];
            u32 b01 = *(const u32*)&wt[g*132     + kw + tig + 4];
            u32 b10 = *(const u32*)&wt[(8+g)*132 + kw + tig];
            u32 b11 = *(const u32*)&wt[(8+g)*132 + kw + tig + 4];
            #pragma unroll
            for(int mt=0; mt<2; mt++){
                int rb = warp*32 + mt*16;
                u32 a0 = *(const u32*)&zb[(rb+g)*36   + kb + tig];
                u32 a1 = *(const u32*)&zb[(rb+g+8)*36 + kb + tig];
                u32 a2 = *(const u32*)&zb[(rb+g)*36   + kb + tig + 4];
                u32 a3 = *(const u32*)&zb[(rb+g+8)*36 + kb + tig + 4];
                mma_tf32(d[mt][0], a0, a1, a2, a3, b00, b01);
                mma_tf32(d[mt][1], a0, a1, a2, a3, b10, b11);
            }
        }
        __syncthreads();
    }
    float mu = sum * (1.f/128.f);
    float rs = rsqrtf(ssq*(1.f/128.f) - mu*mu + EPSV);
    smu[t] = mu; srs[t] = rs;
    __syncthreads();

    // epilogue: LN finalize + fp16 staging (reuse buffer 0)
    __half* sh = (__half*)&zs[0][0];     // [h][128 j]
    #pragma unroll
    for(int mt=0; mt<2; mt++){
        int rA = warp*32 + mt*16 + g;
        int rB = rA + 8;
        float muA = smu[rA], rsA = srs[rA];
        float muB = smu[rB], rsB = srs[rB];
        #pragma unroll
        for(int nt=0; nt<2; nt++){
            int h0 = nt*8 + 2*tig, h1 = h0 + 1;
            sh[h0*128 + rA] = __float2half(rsA*(d[mt][nt][0] - muA*sS[h0]) + sCb[h0]);
            sh[h1*128 + rA] = __float2half(rsA*(d[mt][nt][1] - muA*sS[h1]) + sCb[h1]);
            sh[h0*128 + rB] = __float2half(rsB*(d[mt][nt][2] - muB*sS[h0]) + sCb[h0]);
            sh[h1*128 + rB] = __float2half(rsB*(d[mt][nt][3] - muB*sS[h1]) + sCb[h1]);
        }
    }
    __syncthreads();
    const u32* shp = (const u32*)sh;
    #pragma unroll
    for(int r=0; r<8; r++){
        int lin = r*128 + t;
        int h = lin >> 6, j2 = lin & 63;
        *(u32*)&g_bias[(size_t)h*NP + (size_t)i*NN + j0 + 2*j2] = shp[h*64 + j2];
    }
}

// ------------------------- kernel 5: attention (LDS.128 dots) ---------------
// grid (24, 16): blockIdx.x = q-tile of 32, blockIdx.y = h. 256 threads.
// K/V stride 28 (16B-aligned rows): dots and PV use LDS.128 (6 per score),
// halving wide-LDS instruction count; banks land on all 32 exactly.
__global__ void __launch_bounds__(256, 3) k_attn(const float* __restrict__ mask){
    __shared__ __align__(16) float qs[32*28];
    __shared__ __align__(16) float ks[64*28];
    __shared__ __align__(16) float vs[64*28];
    __shared__ float sbf[32*64];
    __shared__ float smb[NN];
    int t = threadIdx.x;
    int h = blockIdx.y, q0 = blockIdx.x*32;
    const float scale = 0.20412414523193154f;  // 24^-0.5

    for(int idx=t; idx<32*24; idx+=256){
        int qq = idx/24, c = idx - qq*24;
        qs[qq*28 + c] = g_q[(size_t)(q0+qq)*CC + h*CHD + c] * scale;
    }
    for(int idx=t; idx<NN; idx+=256) smb[idx] = INFV*(mask[idx] - 1.f);
    __syncthreads();

    int qq = t >> 3, k8 = t & 7;
    u64 qv[12];
    #pragma unroll
    for(int i4=0; i4<6; i4++){
        float4 v = *(const float4*)&qs[qq*28 + 4*i4];
        qv[2*i4]   = pk2(v.x, v.y);
        qv[2*i4+1] = pk2(v.z, v.w);
    }

    float mx = -1e30f, l = 0.f;
    u64 acc[12];
    #pragma unroll
    for(int i2=0; i2<12; i2++) acc[i2] = 0ull;
    const size_t hNP = (size_t)h*NP;

    for(int kt=0; kt<NN; kt+=64){
        __syncthreads();
        for(int idx=t; idx<64*24; idx+=256){
            int kk = idx/24, c = idx - kk*24;
            ks[kk*28 + c] = g_k[(size_t)(kt+kk)*CC + h*CHD + c];
            vs[kk*28 + c] = g_v[(size_t)(kt+kk)*CC + h*CHD + c];
        }
        #pragma unroll
        for(int r=0; r<4; r++){
            int idx = t + 256*r;
            int q = idx >> 5, k2 = idx & 31;
            u32 pv = *(const u32*)&g_bias[hNP + (size_t)(q0+q)*NN + kt + 2*k2];
            __half2 hh = *(__half2*)&pv;
            float2 fv = __half22float2(hh);
            sbf[q*64 + 2*k2]     = fv.x + smb[kt + 2*k2];
            sbf[q*64 + 2*k2 + 1] = fv.y + smb[kt + 2*k2 + 1];
        }
        __syncthreads();

        // phase 1: 8 independent score chains, LDS.128 K reads
        float sarr[8];
        #pragma unroll
        for(int ii=0; ii<8; ii++){
            int kk = k8 + ii*8;
            u64 d2 = 0ull;
            #pragma unroll
            for(int i4=0; i4<6; i4++){
                float4 kv = *(const float4*)&ks[kk*28 + 4*i4];
                d2 = ffma2(qv[2*i4],   pk2(kv.x, kv.y), d2);
                d2 = ffma2(qv[2*i4+1], pk2(kv.z, kv.w), d2);
            }
            float2 dd = up2(d2);
            sarr[ii] = dd.x + dd.y + sbf[qq*64 + kk];
        }
        // phase 2: one max update per tile
        float tmax = sarr[0];
        #pragma unroll
        for(int ii=1; ii<8; ii++) tmax = fmaxf(tmax, sarr[ii]);
        if(tmax > mx){
            float f = __expf(mx - tmax);
            l *= f;
            u64 f2 = pk2(f, f);
            #pragma unroll
            for(int i2=0; i2<12; i2++) acc[i2] = fmul2(acc[i2], f2);
            mx = tmax;
        }
        // phase 3: exp + PV, LDS.128 V reads
        #pragma unroll
        for(int ii=0; ii<8; ii++){
            int kk = k8 + ii*8;
            float e = __expf(sarr[ii] - mx);
            l += e;
            u64 e2 = pk2(e, e);
            #pragma unroll
            for(int i4=0; i4<6; i4++){
                float4 vv = *(const float4*)&vs[kk*28 + 4*i4];
                acc[2*i4]   = ffma2(pk2(vv.x, vv.y), e2, acc[2*i4]);
                acc[2*i4+1] = ffma2(pk2(vv.z, vv.w), e2, acc[2*i4+1]);
            }
        }
    }
    // merge the 8 lanes that share a q
    #pragma unroll
    for(int off=1; off<8; off<<=1){
        float om = __shfl_xor_sync(~0u, mx, off);
        float ol = __shfl_xor_sync(~0u, l,  off);
        float nm = fmaxf(mx, om);
        float fs = __expf(mx - nm), fo = __expf(om - nm);
        l = l*fs + ol*fo;
        u64 fs2 = pk2(fs, fs), fo2 = pk2(fo, fo);
        #pragma unroll
        for(int i2=0; i2<12; i2++){
            float2 av = up2(acc[i2]);
            float ox = __shfl_xor_sync(~0u, av.x, off);
            float oy = __shfl_xor_sync(~0u, av.y, off);
            acc[i2] = fadd2(fmul2(acc[i2], fs2), fmul2(pk2(ox, oy), fo2));
        }
        mx = nm;
    }
    if(k8 == 0){
        float inv = 1.f / l;
        u64 iv = pk2(inv, inv);
        float* op = g_o + (size_t)(q0+qq)*CC + h*CHD;
        #pragma unroll
        for(int i2=0; i2<12; i2++){
            float2 vv = up2(fmul2(acc[i2], iv));
            *(float2*)&op[2*i2] = vv;
        }
    }
}

// ------------------------- kernel 6: gated output projection ----------------
__global__ void __launch_bounds__(128) k_oproj(const float* __restrict__ Wo,
                                               const float* __restrict__ bo,
                                               float* __restrict__ out){
    __shared__ __align__(16) float As[64*36];
    __shared__ __align__(16) float Bs[32*68];
    int t = threadIdx.x;
    int n0 = blockIdx.x*64, m0 = blockIdx.y*64;
    u64 acc[4][4];
    #pragma unroll
    for(int r=0;r<4;r++){ acc[r][0]=0; acc[r][1]=0; acc[r][2]=0; acc[r][3]=0; }
    int tm = t & 15, tn = t >> 4;

    for(int k0=0; k0<CC; k0+=32){
        __syncthreads();
        #pragma unroll
        for(int r=0; r<4; r++){
            int idx = t + 128*r;
            int row = idx >> 3, c4 = idx & 7;
            size_t aoff = (size_t)(m0+row)*CC + k0 + c4*4;
            float4 ov = *(const float4*)&g_o[aoff];
            float4 gv = *(const float4*)&g_g[aoff];
            float4 av;
            av.x = ov.x * sigmoidf_(gv.x);
            av.y = ov.y * sigmoidf_(gv.y);
            av.z = ov.z * sigmoidf_(gv.z);
            av.w = ov.w * sigmoidf_(gv.w);
            *(float4*)&As[row*36 + c4*4] = av;
            int kr = idx >> 4, n4 = idx & 15;
            float4 bv = *(const float4*)&Wo[(size_t)(k0+kr)*CC + n0 + n4*4];
            *(float4*)&Bs[kr*68 + n4*4] = bv;
        }
        __syncthreads();
        #pragma unroll 8
        for(int kk=0; kk<32; kk++){
            u64 b0 = *(const u64*)&Bs[kk*68 + tn*8 + 0];
            u64 b1 = *(const u64*)&Bs[kk*68 + tn*8 + 2];
            u64 b2 = *(const u64*)&Bs[kk*68 + tn*8 + 4];
            u64 b3 = *(const u64*)&Bs[kk*68 + tn*8 + 6];
            #pragma unroll
            for(int r=0; r<4; r++){
                float av = As[(tm + 16*r)*36 + kk];
                u64 a2 = pk2(av, av);
                acc[r][0] = ffma2(a2, b0, acc[r][0]);
                acc[r][1] = ffma2(a2, b1, acc[r][1]);
                acc[r][2] = ffma2(a2, b2, acc[r][2]);
                acc[r][3] = ffma2(a2, b3, acc[r][3]);
            }
        }
    }
    #pragma unroll
    for(int r=0; r<4; r++){
        int m = m0 + tm + 16*r;
        #pragma unroll
        for(int p=0; p<4; p++){
            int n = n0 + tn*8 + 2*p;
            float2 vv = up2(acc[r][p]);
            vv.x += bo[n]; vv.y += bo[n+1];
            *(float2*)&out[(size_t)m*CC + n] = vv;
        }
    }
}

// ------------------------- launch (serial; bias at profiled idx 3) ----------
extern "C" void kernel_launch(void* const* d_in, const int* in_sizes, int n_in,
                              void* d_out, int out_size){
    const float* a     = (const float*)d_in[0];
    const float* z     = (const float*)d_in[1];
    const float* mask  = (const float*)d_in[2];
    const float* lnaw  = (const float*)d_in[3];
    const float* lnab  = (const float*)d_in[4];
    const float* lnzw  = (const float*)d_in[5];
    const float* lnzb  = (const float*)d_in[6];
    const float* Wz    = (const float*)d_in[7];
    const float* Wq    = (const float*)d_in[8];
    const float* Wk    = (const float*)d_in[9];
    const float* Wv    = (const float*)d_in[10];
    const float* Wg    = (const float*)d_in[11];
    const float* bg    = (const float*)d_in[12];
    const float* Wo    = (const float*)d_in[13];
    const float* bo    = (const float*)d_in[14];
    float* out = (float*)d_out;

    k_prep<<<1, 128>>>(lnzw, lnzb, Wz);                                  // 0
    k_lna<<<96, 256>>>(a, lnaw, lnab);                                   // 1
    k_proj<<<dim3(6, 12, 4), 128>>>(Wq, Wk, Wv, Wg, bg);                 // 2
    k_bias<<<dim3(6, 768), 128>>>(z);                                    // 3 (profiled)
    k_attn<<<dim3(24, 16), 256>>>(mask);                                 // 4
    k_oproj<<<dim3(6, 12), 128>>>(Wo, bo, out);                          // 5
}

// round 12
// speedup vs baseline: 1.4056x; 1.0825x over previous
#include <cuda_runtime.h>
#include <cuda_fp16.h>

#define NN 768
#define CC 384
#define CZd 128
#define HHd 16
#define CHD 24
#define NP (NN*NN)
#define INFV 1e9f
#define EPSV 1e-5f

typedef unsigned long long u64;
typedef unsigned int u32;

// ------------------------- device scratch (no runtime alloc) ----------------
__device__ float g_an[NN*CC];
__device__ float g_q[NN*CC];
__device__ float g_k[NN*CC];
__device__ float g_v[NN*CC];
__device__ float g_g[NN*CC];
__device__ float g_o[NN*CC];
__device__ float g_Wpt[16*128];        // tf32-rounded Wp^T : [h][c]
__device__ float g_S[HHd];
__device__ float g_Cb[HHd];
__device__ __half g_bias[(size_t)HHd*NP];   // [h][i*768 + j]

// ------------------------- packed f32x2 helpers (sm_103a) -------------------
__device__ __forceinline__ u64 pk2(float x, float y){
    u64 r; asm("mov.b64 %0,{%1,%2};" : "=l"(r) : "r"(__float_as_uint(x)), "r"(__float_as_uint(y))); return r;
}
__device__ __forceinline__ float2 up2(u64 v){
    u32 a,b; asm("mov.b64 {%0,%1},%2;" : "=r"(a), "=r"(b) : "l"(v));
    return make_float2(__uint_as_float(a), __uint_as_float(b));
}
__device__ __forceinline__ u64 ffma2(u64 a, u64 b, u64 c){
    u64 d; asm("fma.rn.f32x2 %0,%1,%2,%3;" : "=l"(d) : "l"(a), "l"(b), "l"(c)); return d;
}
__device__ __forceinline__ u64 fmul2(u64 a, u64 b){
    u64 d; asm("mul.rn.f32x2 %0,%1,%2;" : "=l"(d) : "l"(a), "l"(b)); return d;
}
__device__ __forceinline__ u64 fadd2(u64 a, u64 b){
    u64 d; asm("add.rn.f32x2 %0,%1,%2;" : "=l"(d) : "l"(a), "l"(b)); return d;
}
__device__ __forceinline__ float sigmoidf_(float x){ return 1.f/(1.f + __expf(-x)); }

// ------------------------- tf32 warp mma (baseline PTX, sm_103-legal) -------
__device__ __forceinline__ void mma_tf32(float* d, u32 a0, u32 a1, u32 a2, u32 a3,
                                         u32 b0, u32 b1){
    asm volatile(
        "mma.sync.aligned.m16n8k8.row.col.f32.tf32.tf32.f32 "
        "{%0,%1,%2,%3}, {%4,%5,%6,%7}, {%8,%9}, {%0,%1,%2,%3};"
        : "+f"(d[0]), "+f"(d[1]), "+f"(d[2]), "+f"(d[3])
        : "r"(a0), "r"(a1), "r"(a2), "r"(a3), "r"(b0), "r"(b1));
}

// ------------------------- kernel 1: LayerNorm(a) + weight fold (block 96) --
__global__ void k_lnaprep(const float* __restrict__ a, const float* __restrict__ w,
                          const float* __restrict__ b,
                          const float* __restrict__ lnzw, const float* __restrict__ lnzb,
                          const float* __restrict__ Wz){
    if(blockIdx.x == 96){
        __shared__ float sw[128][17];
        __shared__ float sb2[128][17];
        int c = threadIdx.x;
        if(c < 128){
            float w2 = lnzw[c], bb = lnzb[c];
            #pragma unroll
            for(int h=0; h<16; h++){
                float wz = Wz[c*16 + h];
                float wp = w2*wz;
                u32 tf; asm("cvt.rna.tf32.f32 %0, %1;" : "=r"(tf) : "f"(wp));
                float wpr = __uint_as_float(tf);
                g_Wpt[h*128 + c] = wpr;
                sw[c][h] = wpr;
                sb2[c][h] = bb*wz;
            }
        }
        __syncthreads();
        if(c < 16){
            float s = 0.f, cb = 0.f;
            for(int j=0; j<128; j++){ s += sw[j][c]; cb += sb2[j][c]; }
            g_S[c] = s; g_Cb[c] = cb;
        }
        return;
    }
    int warp = threadIdx.x >> 5, lane = threadIdx.x & 31;
    int row = blockIdx.x*8 + warp;
    const float* ar = a + (size_t)row*CC;
    float v[12]; float s = 0.f, ss = 0.f;
    #pragma unroll
    for(int r=0; r<12; r++){ v[r] = ar[lane + r*32]; s += v[r]; ss += v[r]*v[r]; }
    #pragma unroll
    for(int o=16; o; o>>=1){ s += __shfl_xor_sync(~0u, s, o); ss += __shfl_xor_sync(~0u, ss, o); }
    float mu = s * (1.f/CC);
    float rs = rsqrtf(ss*(1.f/CC) - mu*mu + EPSV);
    float* dr = g_an + (size_t)row*CC;
    #pragma unroll
    for(int r=0; r<12; r++){
        int cc = lane + r*32;
        dr[cc] = (v[r]-mu)*rs*w[cc] + b[cc];
    }
}

// ------------------------- kernel 2: QKVG projections -----------------------
__global__ void __launch_bounds__(128) k_proj(const float* __restrict__ Wq,
                                              const float* __restrict__ Wk2,
                                              const float* __restrict__ Wv2,
                                              const float* __restrict__ Wg2,
                                              const float* __restrict__ bg){
    __shared__ __align__(16) float As[64*36];
    __shared__ __align__(16) float Bs[32*68];
    int t = threadIdx.x;
    int n0 = blockIdx.x*64, m0 = blockIdx.y*64, zz = blockIdx.z;
    const float* W = (zz==0) ? Wq : (zz==1) ? Wk2 : (zz==2) ? Wv2 : Wg2;
    float* Cd = (zz==0) ? g_q : (zz==1) ? g_k : (zz==2) ? g_v : g_g;
    u64 acc[4][4];
    #pragma unroll
    for(int r=0;r<4;r++){ acc[r][0]=0; acc[r][1]=0; acc[r][2]=0; acc[r][3]=0; }
    int tm = t & 15, tn = t >> 4;

    for(int k0=0; k0<CC; k0+=32){
        __syncthreads();
        #pragma unroll
        for(int r=0; r<4; r++){
            int idx = t + 128*r;
            int row = idx >> 3, c4 = idx & 7;
            float4 av = *(const float4*)&g_an[(size_t)(m0+row)*CC + k0 + c4*4];
            *(float4*)&As[row*36 + c4*4] = av;
            int kr = idx >> 4, n4 = idx & 15;
            float4 bv = *(const float4*)&W[(size_t)(k0+kr)*CC + n0 + n4*4];
            *(float4*)&Bs[kr*68 + n4*4] = bv;
        }
        __syncthreads();
        #pragma unroll 8
        for(int kk=0; kk<32; kk++){
            u64 b0 = *(const u64*)&Bs[kk*68 + tn*8 + 0];
            u64 b1 = *(const u64*)&Bs[kk*68 + tn*8 + 2];
            u64 b2 = *(const u64*)&Bs[kk*68 + tn*8 + 4];
            u64 b3 = *(const u64*)&Bs[kk*68 + tn*8 + 6];
            #pragma unroll
            for(int r=0; r<4; r++){
                float a = As[(tm + 16*r)*36 + kk];
                u64 a2 = pk2(a, a);
                acc[r][0] = ffma2(a2, b0, acc[r][0]);
                acc[r][1] = ffma2(a2, b1, acc[r][1]);
                acc[r][2] = ffma2(a2, b2, acc[r][2]);
                acc[r][3] = ffma2(a2, b3, acc[r][3]);
            }
        }
    }
    #pragma unroll
    for(int r=0; r<4; r++){
        int m = m0 + tm + 16*r;
        #pragma unroll
        for(int p=0; p<4; p++){
            int n = n0 + tn*8 + 2*p;
            float2 vv = up2(acc[r][p]);
            if(zz == 3){ vv.x += bg[n]; vv.y += bg[n+1]; }
            *(float2*)&Cd[(size_t)m*CC + n] = vv;
        }
    }
}

// ------------------------- kernel 3: pair bias, tf32 mma + double buffer ----
__global__ void __launch_bounds__(128) k_bias(const float* __restrict__ z){
    __shared__ __align__(16) float wt[16*132];       // 8.4KB [h][c]
    __shared__ __align__(16) float zs[2][128*36];    // 2 x 18.4KB ping-pong
    __shared__ float smu[128], srs[128], sS[16], sCb[16];
    int t = threadIdx.x;
    int warp = t >> 5, lane = t & 31, g = lane >> 2, tig = lane & 3;
    int i = blockIdx.y, j0 = blockIdx.x*128;

    #pragma unroll
    for(int r=0; r<4; r++){
        int idx = t + 128*r;
        int h = idx >> 5, cq = idx & 31;
        *(float4*)&wt[h*132 + cq*4] = *(const float4*)&g_Wpt[h*128 + cq*4];
    }
    if(t < 16){ sS[t] = g_S[t]; sCb[t] = g_Cb[t]; }

    const float* zbase = z + ((size_t)i*NN + j0)*CZd;
    float sum = 0.f, ssq = 0.f;
    float d[2][2][4] = {};

    #pragma unroll
    for(int r=0; r<8; r++){
        int idx = t + 128*r;
        int j = idx >> 3, cq = idx & 7;
        *(float4*)&zs[0][j*36 + cq*4] = *(const float4*)(zbase + (size_t)j*CZd + cq*4);
    }
    __syncthreads();

    #pragma unroll
    for(int p=0; p<4; p++){
        if(p < 3){
            #pragma unroll
            for(int r=0; r<8; r++){
                int idx = t + 128*r;
                int j = idx >> 3, cq = idx & 7;
                *(float4*)&zs[(p+1)&1][j*36 + cq*4] =
                    *(const float4*)(zbase + (size_t)j*CZd + (p+1)*32 + cq*4);
            }
        }
        const float* zb = zs[p&1];
        #pragma unroll
        for(int c=0; c<8; c++){
            float4 v = *(const float4*)&zb[t*36 + c*4];
            sum += (v.x + v.y) + (v.z + v.w);
            ssq = fmaf(v.x, v.x, ssq); ssq = fmaf(v.y, v.y, ssq);
            ssq = fmaf(v.z, v.z, ssq); ssq = fmaf(v.w, v.w, ssq);
        }
        #pragma unroll
        for(int kt=0; kt<4; kt++){
            int kb = kt*8;
            int kw = p*32 + kb;
            u32 b00 = *(const u32*)&wt[g*132     + kw + tig];
            u32 b01 = *(const u32*)&wt[g*132     + kw + tig + 4];
            u32 b10 = *(const u32*)&wt[(8+g)*132 + kw + tig];
            u32 b11 = *(const u32*)&wt[(8+g)*132 + kw + tig + 4];
            #pragma unroll
            for(int mt=0; mt<2; mt++){
                int rb = warp*32 + mt*16;
                u32 a0 = *(const u32*)&zb[(rb+g)*36   + kb + tig];
                u32 a1 = *(const u32*)&zb[(rb+g+8)*36 + kb + tig];
                u32 a2 = *(const u32*)&zb[(rb+g)*36   + kb + tig + 4];
                u32 a3 = *(const u32*)&zb[(rb+g+8)*36 + kb + tig + 4];
                mma_tf32(d[mt][0], a0, a1, a2, a3, b00, b01);
                mma_tf32(d[mt][1], a0, a1, a2, a3, b10, b11);
            }
        }
        __syncthreads();
    }
    float mu = sum * (1.f/128.f);
    float rs = rsqrtf(ssq*(1.f/128.f) - mu*mu + EPSV);
    smu[t] = mu; srs[t] = rs;
    __syncthreads();

    __half* sh = (__half*)&zs[0][0];     // [h][128 j]
    #pragma unroll
    for(int mt=0; mt<2; mt++){
        int rA = warp*32 + mt*16 + g;
        int rB = rA + 8;
        float muA = smu[rA], rsA = srs[rA];
        float muB = smu[rB], rsB = srs[rB];
        #pragma unroll
        for(int nt=0; nt<2; nt++){
            int h0 = nt*8 + 2*tig, h1 = h0 + 1;
            sh[h0*128 + rA] = __float2half(rsA*(d[mt][nt][0] - muA*sS[h0]) + sCb[h0]);
            sh[h1*128 + rA] = __float2half(rsA*(d[mt][nt][1] - muA*sS[h1]) + sCb[h1]);
            sh[h0*128 + rB] = __float2half(rsB*(d[mt][nt][2] - muB*sS[h0]) + sCb[h0]);
            sh[h1*128 + rB] = __float2half(rsB*(d[mt][nt][3] - muB*sS[h1]) + sCb[h1]);
        }
    }
    __syncthreads();
    const u32* shp = (const u32*)sh;
    #pragma unroll
    for(int r=0; r<8; r++){
        int lin = r*128 + t;
        int h = lin >> 6, j2 = lin & 63;
        *(u32*)&g_bias[(size_t)h*NP + (size_t)i*NN + j0 + 2*j2] = shp[h*64 + j2];
    }
}

// ------------------------- kernel 4: attention, tf32 mma QK^T ---------------
// grid (24, 16): blockIdx.x = q-tile of 32, blockIdx.y = h. 256 threads.
// Per k-tile: 8 warps (2m x 4n) compute 32x64 scores via mma into sraw;
// then the scalar online-softmax + PV phase reads sraw + sbf (LDS.32).
__global__ void __launch_bounds__(256, 3) k_attn(const float* __restrict__ mask){
    __shared__ __align__(16) float qs[32*28];
    __shared__ __align__(16) float ks[64*28];
    __shared__ __align__(16) float vs[64*28];
    __shared__ float sbf[32*64];
    __shared__ float sraw[32*68];
    __shared__ float smb[NN];
    int t = threadIdx.x;
    int h = blockIdx.y, q0 = blockIdx.x*32;
    const float scale = 0.20412414523193154f;  // 24^-0.5
    int warp = t >> 5, lane = t & 31, g = lane >> 2, tig = lane & 3;
    int wm = warp >> 2, wn = warp & 3;

    for(int idx=t; idx<32*24; idx+=256){
        int qq = idx/24, c = idx - qq*24;
        qs[qq*28 + c] = g_q[(size_t)(q0+qq)*CC + h*CHD + c] * scale;
    }
    for(int idx=t; idx<NN; idx+=256) smb[idx] = INFV*(mask[idx] - 1.f);
    __syncthreads();

    int qq = t >> 3, k8 = t & 7;
    float mx = -1e30f, l = 0.f;
    u64 acc[12];
    #pragma unroll
    for(int i2=0; i2<12; i2++) acc[i2] = 0ull;
    const size_t hNP = (size_t)h*NP;
    int aR  = (wm*16 + g)*28, aR8 = (wm*16 + 8 + g)*28;
    int bR  = (wn*16 + g)*28, bR8 = (wn*16 + 8 + g)*28;

    for(int kt0=0; kt0<NN; kt0+=64){
        __syncthreads();
        for(int idx=t; idx<64*24; idx+=256){
            int kk = idx/24, c = idx - kk*24;
            ks[kk*28 + c] = g_k[(size_t)(kt0+kk)*CC + h*CHD + c];
            vs[kk*28 + c] = g_v[(size_t)(kt0+kk)*CC + h*CHD + c];
        }
        #pragma unroll
        for(int r=0; r<4; r++){
            int idx = t + 256*r;
            int q = idx >> 5, k2 = idx & 31;
            u32 pv = *(const u32*)&g_bias[hNP + (size_t)(q0+q)*NN + kt0 + 2*k2];
            __half2 hh = *(__half2*)&pv;
            float2 fv = __half22float2(hh);
            sbf[q*64 + 2*k2]     = fv.x + smb[kt0 + 2*k2];
            sbf[q*64 + 2*k2 + 1] = fv.y + smb[kt0 + 2*k2 + 1];
        }
        __syncthreads();

        // mma score phase: warp (wm, wn) computes rows wm*16..+16, cols wn*16..+16
        float d0[4] = {0.f,0.f,0.f,0.f};
        float d1[4] = {0.f,0.f,0.f,0.f};
        #pragma unroll
        for(int kt=0; kt<3; kt++){
            int kb = kt*8;
            u32 a0 = *(const u32*)&qs[aR  + kb + tig];
            u32 a1 = *(const u32*)&qs[aR8 + kb + tig];
            u32 a2 = *(const u32*)&qs[aR  + kb + tig + 4];
            u32 a3 = *(const u32*)&qs[aR8 + kb + tig + 4];
            u32 b00 = *(const u32*)&ks[bR  + kb + tig];
            u32 b01 = *(const u32*)&ks[bR  + kb + tig + 4];
            u32 b10 = *(const u32*)&ks[bR8 + kb + tig];
            u32 b11 = *(const u32*)&ks[bR8 + kb + tig + 4];
            mma_tf32(d0, a0, a1, a2, a3, b00, b01);
            mma_tf32(d1, a0, a1, a2, a3, b10, b11);
        }
        {
            int r0 = wm*16 + g, c0 = wn*16 + 2*tig;
            sraw[r0*68 + c0]         = d0[0];
            sraw[r0*68 + c0 + 1]     = d0[1];
            sraw[(r0+8)*68 + c0]     = d0[2];
            sraw[(r0+8)*68 + c0 + 1] = d0[3];
            sraw[r0*68 + c0 + 8]     = d1[0];
            sraw[r0*68 + c0 + 9]     = d1[1];
            sraw[(r0+8)*68 + c0 + 8] = d1[2];
            sraw[(r0+8)*68 + c0 + 9] = d1[3];
        }
        __syncthreads();

        // scalar phase: scores from smem, online softmax + PV
        float sarr[8];
        #pragma unroll
        for(int ii=0; ii<8; ii++){
            int kk = k8 + ii*8;
            sarr[ii] = sraw[qq*68 + kk] + sbf[qq*64 + kk];
        }
        float tmax = sarr[0];
        #pragma unroll
        for(int ii=1; ii<8; ii++) tmax = fmaxf(tmax, sarr[ii]);
        if(tmax > mx){
            float f = __expf(mx - tmax);
            l *= f;
            u64 f2 = pk2(f, f);
            #pragma unroll
            for(int i2=0; i2<12; i2++) acc[i2] = fmul2(acc[i2], f2);
            mx = tmax;
        }
        #pragma unroll
        for(int ii=0; ii<8; ii++){
            int kk = k8 + ii*8;
            float e = __expf(sarr[ii] - mx);
            l += e;
            u64 e2 = pk2(e, e);
            #pragma unroll
            for(int i4=0; i4<6; i4++){
                float4 vv = *(const float4*)&vs[kk*28 + 4*i4];
                acc[2*i4]   = ffma2(pk2(vv.x, vv.y), e2, acc[2*i4]);
                acc[2*i4+1] = ffma2(pk2(vv.z, vv.w), e2, acc[2*i4+1]);
            }
        }
    }
    // merge the 8 lanes that share a q
    #pragma unroll
    for(int off=1; off<8; off<<=1){
        float om = __shfl_xor_sync(~0u, mx, off);
        float ol = __shfl_xor_sync(~0u, l,  off);
        float nm = fmaxf(mx, om);
        float fs = __expf(mx - nm), fo = __expf(om - nm);
        l = l*fs + ol*fo;
        u64 fs2 = pk2(fs, fs), fo2 = pk2(fo, fo);
        #pragma unroll
        for(int i2=0; i2<12; i2++){
            float2 av = up2(acc[i2]);
            float ox = __shfl_xor_sync(~0u, av.x, off);
            float oy = __shfl_xor_sync(~0u, av.y, off);
            acc[i2] = fadd2(fmul2(acc[i2], fs2), fmul2(pk2(ox, oy), fo2));
        }
        mx = nm;
    }
    if(k8 == 0){
        float inv = 1.f / l;
        u64 iv = pk2(inv, inv);
        float* op = g_o + (size_t)(q0+qq)*CC + h*CHD;
        #pragma unroll
        for(int i2=0; i2<12; i2++){
            float2 vv = up2(fmul2(acc[i2], iv));
            *(float2*)&op[2*i2] = vv;
        }
    }
}

// ------------------------- kernel 5: gated output projection ----------------
__global__ void __launch_bounds__(128) k_oproj(const float* __restrict__ Wo,
                                               const float* __restrict__ bo,
                                               float* __restrict__ out){
    __shared__ __align__(16) float As[64*36];
    __shared__ __align__(16) float Bs[32*68];
    int t = threadIdx.x;
    int n0 = blockIdx.x*64, m0 = blockIdx.y*64;
    u64 acc[4][4];
    #pragma unroll
    for(int r=0;r<4;r++){ acc[r][0]=0; acc[r][1]=0; acc[r][2]=0; acc[r][3]=0; }
    int tm = t & 15, tn = t >> 4;

    for(int k0=0; k0<CC; k0+=32){
        __syncthreads();
        #pragma unroll
        for(int r=0; r<4; r++){
            int idx = t + 128*r;
            int row = idx >> 3, c4 = idx & 7;
            size_t aoff = (size_t)(m0+row)*CC + k0 + c4*4;
            float4 ov = *(const float4*)&g_o[aoff];
            float4 gv = *(const float4*)&g_g[aoff];
            float4 av;
            av.x = ov.x * sigmoidf_(gv.x);
            av.y = ov.y * sigmoidf_(gv.y);
            av.z = ov.z * sigmoidf_(gv.z);
            av.w = ov.w * sigmoidf_(gv.w);
            *(float4*)&As[row*36 + c4*4] = av;
            int kr = idx >> 4, n4 = idx & 15;
            float4 bv = *(const float4*)&Wo[(size_t)(k0+kr)*CC + n0 + n4*4];
            *(float4*)&Bs[kr*68 + n4*4] = bv;
        }
        __syncthreads();
        #pragma unroll 8
        for(int kk=0; kk<32; kk++){
            u64 b0 = *(const u64*)&Bs[kk*68 + tn*8 + 0];
            u64 b1 = *(const u64*)&Bs[kk*68 + tn*8 + 2];
            u64 b2 = *(const u64*)&Bs[kk*68 + tn*8 + 4];
            u64 b3 = *(const u64*)&Bs[kk*68 + tn*8 + 6];
            #pragma unroll
            for(int r=0; r<4; r++){
                float av = As[(tm + 16*r)*36 + kk];
                u64 a2 = pk2(av, av);
                acc[r][0] = ffma2(a2, b0, acc[r][0]);
                acc[r][1] = ffma2(a2, b1, acc[r][1]);
                acc[r][2] = ffma2(a2, b2, acc[r][2]);
                acc[r][3] = ffma2(a2, b3, acc[r][3]);
            }
        }
    }
    #pragma unroll
    for(int r=0; r<4; r++){
        int m = m0 + tm + 16*r;
        #pragma unroll
        for(int p=0; p<4; p++){
            int n = n0 + tn*8 + 2*p;
            float2 vv = up2(acc[r][p]);
            vv.x += bo[n]; vv.y += bo[n+1];
            *(float2*)&out[(size_t)m*CC + n] = vv;
        }
    }
}

// ------------------------- launch (serial; attn at profiled idx 3) ----------
extern "C" void kernel_launch(void* const* d_in, const int* in_sizes, int n_in,
                              void* d_out, int out_size){
    const float* a     = (const float*)d_in[0];
    const float* z     = (const float*)d_in[1];
    const float* mask  = (const float*)d_in[2];
    const float* lnaw  = (const float*)d_in[3];
    const float* lnab  = (const float*)d_in[4];
    const float* lnzw  = (const float*)d_in[5];
    const float* lnzb  = (const float*)d_in[6];
    const float* Wz    = (const float*)d_in[7];
    const float* Wq    = (const float*)d_in[8];
    const float* Wk    = (const float*)d_in[9];
    const float* Wv    = (const float*)d_in[10];
    const float* Wg    = (const float*)d_in[11];
    const float* bg    = (const float*)d_in[12];
    const float* Wo    = (const float*)d_in[13];
    const float* bo    = (const float*)d_in[14];
    float* out = (float*)d_out;

    k_lnaprep<<<97, 256>>>(a, lnaw, lnab, lnzw, lnzb, Wz);               // 0
    k_proj<<<dim3(6, 12, 4), 128>>>(Wq, Wk, Wv, Wg, bg);                 // 1
    k_bias<<<dim3(6, 768), 128>>>(z);                                    // 2
    k_attn<<<dim3(24, 16), 256>>>(mask);                                 // 3 (profiled)
    k_oproj<<<dim3(6, 12), 128>>>(Wo, bo, out);                          // 4
}

// round 13
// speedup vs baseline: 1.4088x; 1.0023x over previous
#include <cuda_runtime.h>
#include <cuda_fp16.h>

#define NN 768
#define CC 384
#define CZd 128
#define HHd 16
#define CHD 24
#define NP (NN*NN)
#define INFV 1e9f
#define EPSV 1e-5f

typedef unsigned long long u64;
typedef unsigned int u32;

// ------------------------- device scratch (no runtime alloc) ----------------
__device__ float g_an[NN*CC];
__device__ float g_q[NN*CC];
__device__ float g_k[NN*CC];
__device__ float g_v[NN*CC];
__device__ float g_g[NN*CC];
__device__ float g_o[NN*CC];
__device__ float g_Wpt[16*128];        // tf32-rounded Wp^T : [h][c]
__device__ float g_S[HHd];
__device__ float g_Cb[HHd];
__device__ __half g_bias[(size_t)HHd*NP];   // [h][i*768 + j]

// ------------------------- packed f32x2 helpers (sm_103a) -------------------
__device__ __forceinline__ u64 pk2(float x, float y){
    u64 r; asm("mov.b64 %0,{%1,%2};" : "=l"(r) : "r"(__float_as_uint(x)), "r"(__float_as_uint(y))); return r;
}
__device__ __forceinline__ float2 up2(u64 v){
    u32 a,b; asm("mov.b64 {%0,%1},%2;" : "=r"(a), "=r"(b) : "l"(v));
    return make_float2(__uint_as_float(a), __uint_as_float(b));
}
__device__ __forceinline__ u64 ffma2(u64 a, u64 b, u64 c){
    u64 d; asm("fma.rn.f32x2 %0,%1,%2,%3;" : "=l"(d) : "l"(a), "l"(b), "l"(c)); return d;
}
__device__ __forceinline__ u64 fmul2(u64 a, u64 b){
    u64 d; asm("mul.rn.f32x2 %0,%1,%2;" : "=l"(d) : "l"(a), "l"(b)); return d;
}
__device__ __forceinline__ u64 fadd2(u64 a, u64 b){
    u64 d; asm("add.rn.f32x2 %0,%1,%2;" : "=l"(d) : "l"(a), "l"(b)); return d;
}
__device__ __forceinline__ float sigmoidf_(float x){ return 1.f/(1.f + __expf(-x)); }

// ------------------------- tf32 warp mma (baseline PTX, sm_103-legal) -------
__device__ __forceinline__ void mma_tf32(float* d, u32 a0, u32 a1, u32 a2, u32 a3,
                                         u32 b0, u32 b1){
    asm volatile(
        "mma.sync.aligned.m16n8k8.row.col.f32.tf32.tf32.f32 "
        "{%0,%1,%2,%3}, {%4,%5,%6,%7}, {%8,%9}, {%0,%1,%2,%3};"
        : "+f"(d[0]), "+f"(d[1]), "+f"(d[2]), "+f"(d[3])
        : "r"(a0), "r"(a1), "r"(a2), "r"(a3), "r"(b0), "r"(b1));
}

// ------------------------- kernel 1: LayerNorm(a) + weight fold (block 96) --
__global__ void k_lnaprep(const float* __restrict__ a, const float* __restrict__ w,
                          const float* __restrict__ b,
                          const float* __restrict__ lnzw, const float* __restrict__ lnzb,
                          const float* __restrict__ Wz){
    if(blockIdx.x == 96){
        __shared__ float sw[128][17];
        __shared__ float sb2[128][17];
        int c = threadIdx.x;
        if(c < 128){
            float w2 = lnzw[c], bb = lnzb[c];
            #pragma unroll
            for(int h=0; h<16; h++){
                float wz = Wz[c*16 + h];
                float wp = w2*wz;
                u32 tf; asm("cvt.rna.tf32.f32 %0, %1;" : "=r"(tf) : "f"(wp));
                float wpr = __uint_as_float(tf);
                g_Wpt[h*128 + c] = wpr;
                sw[c][h] = wpr;
                sb2[c][h] = bb*wz;
            }
        }
        __syncthreads();
        if(c < 16){
            float s = 0.f, cb = 0.f;
            for(int j=0; j<128; j++){ s += sw[j][c]; cb += sb2[j][c]; }
            g_S[c] = s; g_Cb[c] = cb;
        }
        return;
    }
    int warp = threadIdx.x >> 5, lane = threadIdx.x & 31;
    int row = blockIdx.x*8 + warp;
    const float* ar = a + (size_t)row*CC;
    float v[12]; float s = 0.f, ss = 0.f;
    #pragma unroll
    for(int r=0; r<12; r++){ v[r] = ar[lane + r*32]; s += v[r]; ss += v[r]*v[r]; }
    #pragma unroll
    for(int o=16; o; o>>=1){ s += __shfl_xor_sync(~0u, s, o); ss += __shfl_xor_sync(~0u, ss, o); }
    float mu = s * (1.f/CC);
    float rs = rsqrtf(ss*(1.f/CC) - mu*mu + EPSV);
    float* dr = g_an + (size_t)row*CC;
    #pragma unroll
    for(int r=0; r<12; r++){
        int cc = lane + r*32;
        dr[cc] = (v[r]-mu)*rs*w[cc] + b[cc];
    }
}

// ------------------------- kernel 2: QKVG projections -----------------------
__global__ void __launch_bounds__(128) k_proj(const float* __restrict__ Wq,
                                              const float* __restrict__ Wk2,
                                              const float* __restrict__ Wv2,
                                              const float* __restrict__ Wg2,
                                              const float* __restrict__ bg){
    __shared__ __align__(16) float As[64*36];
    __shared__ __align__(16) float Bs[32*68];
    int t = threadIdx.x;
    int n0 = blockIdx.x*64, m0 = blockIdx.y*64, zz = blockIdx.z;
    const float* W = (zz==0) ? Wq : (zz==1) ? Wk2 : (zz==2) ? Wv2 : Wg2;
    float* Cd = (zz==0) ? g_q : (zz==1) ? g_k : (zz==2) ? g_v : g_g;
    u64 acc[4][4];
    #pragma unroll
    for(int r=0;r<4;r++){ acc[r][0]=0; acc[r][1]=0; acc[r][2]=0; acc[r][3]=0; }
    int tm = t & 15, tn = t >> 4;

    for(int k0=0; k0<CC; k0+=32){
        __syncthreads();
        #pragma unroll
        for(int r=0; r<4; r++){
            int idx = t + 128*r;
            int row = idx >> 3, c4 = idx & 7;
            float4 av = *(const float4*)&g_an[(size_t)(m0+row)*CC + k0 + c4*4];
            *(float4*)&As[row*36 + c4*4] = av;
            int kr = idx >> 4, n4 = idx & 15;
            float4 bv = *(const float4*)&W[(size_t)(k0+kr)*CC + n0 + n4*4];
            *(float4*)&Bs[kr*68 + n4*4] = bv;
        }
        __syncthreads();
        #pragma unroll 8
        for(int kk=0; kk<32; kk++){
            u64 b0 = *(const u64*)&Bs[kk*68 + tn*8 + 0];
            u64 b1 = *(const u64*)&Bs[kk*68 + tn*8 + 2];
            u64 b2 = *(const u64*)&Bs[kk*68 + tn*8 + 4];
            u64 b3 = *(const u64*)&Bs[kk*68 + tn*8 + 6];
            #pragma unroll
            for(int r=0; r<4; r++){
                float a = As[(tm + 16*r)*36 + kk];
                u64 a2 = pk2(a, a);
                acc[r][0] = ffma2(a2, b0, acc[r][0]);
                acc[r][1] = ffma2(a2, b1, acc[r][1]);
                acc[r][2] = ffma2(a2, b2, acc[r][2]);
                acc[r][3] = ffma2(a2, b3, acc[r][3]);
            }
        }
    }
    #pragma unroll
    for(int r=0; r<4; r++){
        int m = m0 + tm + 16*r;
        #pragma unroll
        for(int p=0; p<4; p++){
            int n = n0 + tn*8 + 2*p;
            float2 vv = up2(acc[r][p]);
            if(zz == 3){ vv.x += bg[n]; vv.y += bg[n+1]; }
            *(float2*)&Cd[(size_t)m*CC + n] = vv;
        }
    }
}

// ------------------------- kernel 3: pair bias, tf32 mma + double buffer ----
__global__ void __launch_bounds__(128) k_bias(const float* __restrict__ z){
    __shared__ __align__(16) float wt[16*132];       // 8.4KB [h][c]
    __shared__ __align__(16) float zs[2][128*36];    // 2 x 18.4KB ping-pong
    __shared__ float smu[128], srs[128], sS[16], sCb[16];
    int t = threadIdx.x;
    int warp = t >> 5, lane = t & 31, g = lane >> 2, tig = lane & 3;
    int i = blockIdx.y, j0 = blockIdx.x*128;

    #pragma unroll
    for(int r=0; r<4; r++){
        int idx = t + 128*r;
        int h = idx >> 5, cq = idx & 31;
        *(float4*)&wt[h*132 + cq*4] = *(const float4*)&g_Wpt[h*128 + cq*4];
    }
    if(t < 16){ sS[t] = g_S[t]; sCb[t] = g_Cb[t]; }

    const float* zbase = z + ((size_t)i*NN + j0)*CZd;
    float sum = 0.f, ssq = 0.f;
    float d[2][2][4] = {};

    #pragma unroll
    for(int r=0; r<8; r++){
        int idx = t + 128*r;
        int j = idx >> 3, cq = idx & 7;
        *(float4*)&zs[0][j*36 + cq*4] = *(const float4*)(zbase + (size_t)j*CZd + cq*4);
    }
    __syncthreads();

    #pragma unroll
    for(int p=0; p<4; p++){
        if(p < 3){
            #pragma unroll
            for(int r=0; r<8; r++){
                int idx = t + 128*r;
                int j = idx >> 3, cq = idx & 7;
                *(float4*)&zs[(p+1)&1][j*36 + cq*4] =
                    *(const float4*)(zbase + (size_t)j*CZd + (p+1)*32 + cq*4);
            }
        }
        const float* zb = zs[p&1];
        #pragma unroll
        for(int c=0; c<8; c++){
            float4 v = *(const float4*)&zb[t*36 + c*4];
            sum += (v.x + v.y) + (v.z + v.w);
            ssq = fmaf(v.x, v.x, ssq); ssq = fmaf(v.y, v.y, ssq);
            ssq = fmaf(v.z, v.z, ssq); ssq = fmaf(v.w, v.w, ssq);
        }
        #pragma unroll
        for(int kt=0; kt<4; kt++){
            int kb = kt*8;
            int kw = p*32 + kb;
            u32 b00 = *(const u32*)&wt[g*132     + kw + tig];
            u32 b01 = *(const u32*)&wt[g*132     + kw + tig + 4];
            u32 b10 = *(const u32*)&wt[(8+g)*132 + kw + tig];
            u32 b11 = *(const u32*)&wt[(8+g)*132 + kw + tig + 4];
            #pragma unroll
            for(int mt=0; mt<2; mt++){
                int rb = warp*32 + mt*16;
                u32 a0 = *(const u32*)&zb[(rb+g)*36   + kb + tig];
                u32 a1 = *(const u32*)&zb[(rb+g+8)*36 + kb + tig];
                u32 a2 = *(const u32*)&zb[(rb+g)*36   + kb + tig + 4];
                u32 a3 = *(const u32*)&zb[(rb+g+8)*36 + kb + tig + 4];
                mma_tf32(d[mt][0], a0, a1, a2, a3, b00, b01);
                mma_tf32(d[mt][1], a0, a1, a2, a3, b10, b11);
            }
        }
        __syncthreads();
    }
    float mu = sum * (1.f/128.f);
    float rs = rsqrtf(ssq*(1.f/128.f) - mu*mu + EPSV);
    smu[t] = mu; srs[t] = rs;
    __syncthreads();

    __half* sh = (__half*)&zs[0][0];     // [h][128 j]
    #pragma unroll
    for(int mt=0; mt<2; mt++){
        int rA = warp*32 + mt*16 + g;
        int rB = rA + 8;
        float muA = smu[rA], rsA = srs[rA];
        float muB = smu[rB], rsB = srs[rB];
        #pragma unroll
        for(int nt=0; nt<2; nt++){
            int h0 = nt*8 + 2*tig, h1 = h0 + 1;
            sh[h0*128 + rA] = __float2half(rsA*(d[mt][nt][0] - muA*sS[h0]) + sCb[h0]);
            sh[h1*128 + rA] = __float2half(rsA*(d[mt][nt][1] - muA*sS[h1]) + sCb[h1]);
            sh[h0*128 + rB] = __float2half(rsB*(d[mt][nt][2] - muB*sS[h0]) + sCb[h0]);
            sh[h1*128 + rB] = __float2half(rsB*(d[mt][nt][3] - muB*sS[h1]) + sCb[h1]);
        }
    }
    __syncthreads();
    const u32* shp = (const u32*)sh;
    #pragma unroll
    for(int r=0; r<8; r++){
        int lin = r*128 + t;
        int h = lin >> 6, j2 = lin & 63;
        *(u32*)&g_bias[(size_t)h*NP + (size_t)i*NN + j0 + 2*j2] = shp[h*64 + j2];
    }
}

// ------------------------- kernel 4: attention, tf32 mma QK^T ---------------
// grid (24, 16): blockIdx.x = q-tile of 32, blockIdx.y = h. 256 threads.
// Per k-tile: 8 warps (2m x 4n) compute 32x64 scores via mma into sraw;
// then the scalar online-softmax + PV phase reads sraw + sbf (LDS.32).
__global__ void __launch_bounds__(256, 3) k_attn(const float* __restrict__ mask){
    __shared__ __align__(16) float qs[32*28];
    __shared__ __align__(16) float ks[64*28];
    __shared__ __align__(16) float vs[64*28];
    __shared__ float sbf[32*64];
    __shared__ float sraw[32*68];
    __shared__ float smb[NN];
    int t = threadIdx.x;
    int h = blockIdx.y, q0 = blockIdx.x*32;
    const float scale = 0.20412414523193154f;  // 24^-0.5
    int warp = t >> 5, lane = t & 31, g = lane >> 2, tig = lane & 3;
    int wm = warp >> 2, wn = warp & 3;

    for(int idx=t; idx<32*24; idx+=256){
        int qq = idx/24, c = idx - qq*24;
        qs[qq*28 + c] = g_q[(size_t)(q0+qq)*CC + h*CHD + c] * scale;
    }
    for(int idx=t; idx<NN; idx+=256) smb[idx] = INFV*(mask[idx] - 1.f);
    __syncthreads();

    int qq = t >> 3, k8 = t & 7;
    float mx = -1e30f, l = 0.f;
    u64 acc[12];
    #pragma unroll
    for(int i2=0; i2<12; i2++) acc[i2] = 0ull;
    const size_t hNP = (size_t)h*NP;
    int aR  = (wm*16 + g)*28, aR8 = (wm*16 + 8 + g)*28;
    int bR  = (wn*16 + g)*28, bR8 = (wn*16 + 8 + g)*28;

    for(int kt0=0; kt0<NN; kt0+=64){
        __syncthreads();
        for(int idx=t; idx<64*24; idx+=256){
            int kk = idx/24, c = idx - kk*24;
            ks[kk*28 + c] = g_k[(size_t)(kt0+kk)*CC + h*CHD + c];
            vs[kk*28 + c] = g_v[(size_t)(kt0+kk)*CC + h*CHD + c];
        }
        #pragma unroll
        for(int r=0; r<4; r++){
            int idx = t + 256*r;
            int q = idx >> 5, k2 = idx & 31;
            u32 pv = *(const u32*)&g_bias[hNP + (size_t)(q0+q)*NN + kt0 + 2*k2];
            __half2 hh = *(__half2*)&pv;
            float2 fv = __half22float2(hh);
            sbf[q*64 + 2*k2]     = fv.x + smb[kt0 + 2*k2];
            sbf[q*64 + 2*k2 + 1] = fv.y + smb[kt0 + 2*k2 + 1];
        }
        __syncthreads();

        // mma score phase: warp (wm, wn) computes rows wm*16..+16, cols wn*16..+16
        float d0[4] = {0.f,0.f,0.f,0.f};
        float d1[4] = {0.f,0.f,0.f,0.f};
        #pragma unroll
        for(int kt=0; kt<3; kt++){
            int kb = kt*8;
            u32 a0 = *(const u32*)&qs[aR  + kb + tig];
            u32 a1 = *(const u32*)&qs[aR8 + kb + tig];
            u32 a2 = *(const u32*)&qs[aR  + kb + tig + 4];
            u32 a3 = *(const u32*)&qs[aR8 + kb + tig + 4];
            u32 b00 = *(const u32*)&ks[bR  + kb + tig];
            u32 b01 = *(const u32*)&ks[bR  + kb + tig + 4];
            u32 b10 = *(const u32*)&ks[bR8 + kb + tig];
            u32 b11 = *(const u32*)&ks[bR8 + kb + tig + 4];
            mma_tf32(d0, a0, a1, a2, a3, b00, b01);
            mma_tf32(d1, a0, a1, a2, a3, b10, b11);
        }
        {
            int r0 = wm*16 + g, c0 = wn*16 + 2*tig;
            sraw[r0*68 + c0]         = d0[0];
            sraw[r0*68 + c0 + 1]     = d0[1];
            sraw[(r0+8)*68 + c0]     = d0[2];
            sraw[(r0+8)*68 + c0 + 1] = d0[3];
            sraw[r0*68 + c0 + 8]     = d1[0];
            sraw[r0*68 + c0 + 9]     = d1[1];
            sraw[(r0+8)*68 + c0 + 8] = d1[2];
            sraw[(r0+8)*68 + c0 + 9] = d1[3];
        }
        __syncthreads();

        // scalar phase: scores from smem, online softmax + PV
        float sarr[8];
        #pragma unroll
        for(int ii=0; ii<8; ii++){
            int kk = k8 + ii*8;
            sarr[ii] = sraw[qq*68 + kk] + sbf[qq*64 + kk];
        }
        float tmax = sarr[0];
        #pragma unroll
        for(int ii=1; ii<8; ii++) tmax = fmaxf(tmax, sarr[ii]);
        if(tmax > mx){
            float f = __expf(mx - tmax);
            l *= f;
            u64 f2 = pk2(f, f);
            #pragma unroll
            for(int i2=0; i2<12; i2++) acc[i2] = fmul2(acc[i2], f2);
            mx = tmax;
        }
        #pragma unroll
        for(int ii=0; ii<8; ii++){
            int kk = k8 + ii*8;
            float e = __expf(sarr[ii] - mx);
            l += e;
            u64 e2 = pk2(e, e);
            #pragma unroll
            for(int i4=0; i4<6; i4++){
                float4 vv = *(const float4*)&vs[kk*28 + 4*i4];
                acc[2*i4]   = ffma2(pk2(vv.x, vv.y), e2, acc[2*i4]);
                acc[2*i4+1] = ffma2(pk2(vv.z, vv.w), e2, acc[2*i4+1]);
            }
        }
    }
    // merge the 8 lanes that share a q
    #pragma unroll
    for(int off=1; off<8; off<<=1){
        float om = __shfl_xor_sync(~0u, mx, off);
        float ol = __shfl_xor_sync(~0u, l,  off);
        float nm = fmaxf(mx, om);
        float fs = __expf(mx - nm), fo = __expf(om - nm);
        l = l*fs + ol*fo;
        u64 fs2 = pk2(fs, fs), fo2 = pk2(fo, fo);
        #pragma unroll
        for(int i2=0; i2<12; i2++){
            float2 av = up2(acc[i2]);
            float ox = __shfl_xor_sync(~0u, av.x, off);
            float oy = __shfl_xor_sync(~0u, av.y, off);
            acc[i2] = fadd2(fmul2(acc[i2], fs2), fmul2(pk2(ox, oy), fo2));
        }
        mx = nm;
    }
    if(k8 == 0){
        float inv = 1.f / l;
        u64 iv = pk2(inv, inv);
        float* op = g_o + (size_t)(q0+qq)*CC + h*CHD;
        #pragma unroll
        for(int i2=0; i2<12; i2++){
            float2 vv = up2(fmul2(acc[i2], iv));
            *(float2*)&op[2*i2] = vv;
        }
    }
}

// ------------------------- kernel 5: gated output projection ----------------
__global__ void __launch_bounds__(128) k_oproj(const float* __restrict__ Wo,
                                               const float* __restrict__ bo,
                                               float* __restrict__ out){
    __shared__ __align__(16) float As[64*36];
    __shared__ __align__(16) float Bs[32*68];
    int t = threadIdx.x;
    int n0 = blockIdx.x*64, m0 = blockIdx.y*64;
    u64 acc[4][4];
    #pragma unroll
    for(int r=0;r<4;r++){ acc[r][0]=0; acc[r][1]=0; acc[r][2]=0; acc[r][3]=0; }
    int tm = t & 15, tn = t >> 4;

    for(int k0=0; k0<CC; k0+=32){
        __syncthreads();
        #pragma unroll
        for(int r=0; r<4; r++){
            int idx = t + 128*r;
            int row = idx >> 3, c4 = idx & 7;
            size_t aoff = (size_t)(m0+row)*CC + k0 + c4*4;
            float4 ov = *(const float4*)&g_o[aoff];
            float4 gv = *(const float4*)&g_g[aoff];
            float4 av;
            av.x = ov.x * sigmoidf_(gv.x);
            av.y = ov.y * sigmoidf_(gv.y);
            av.z = ov.z * sigmoidf_(gv.z);
            av.w = ov.w * sigmoidf_(gv.w);
            *(float4*)&As[row*36 + c4*4] = av;
            int kr = idx >> 4, n4 = idx & 15;
            float4 bv = *(const float4*)&Wo[(size_t)(k0+kr)*CC + n0 + n4*4];
            *(float4*)&Bs[kr*68 + n4*4] = bv;
        }
        __syncthreads();
        #pragma unroll 8
        for(int kk=0; kk<32; kk++){
            u64 b0 = *(const u64*)&Bs[kk*68 + tn*8 + 0];
            u64 b1 = *(const u64*)&Bs[kk*68 + tn*8 + 2];
            u64 b2 = *(const u64*)&Bs[kk*68 + tn*8 + 4];
            u64 b3 = *(const u64*)&Bs[kk*68 + tn*8 + 6];
            #pragma unroll
            for(int r=0; r<4; r++){
                float av = As[(tm + 16*r)*36 + kk];
                u64 a2 = pk2(av, av);
                acc[r][0] = ffma2(a2, b0, acc[r][0]);
                acc[r][1] = ffma2(a2, b1, acc[r][1]);
                acc[r][2] = ffma2(a2, b2, acc[r][2]);
                acc[r][3] = ffma2(a2, b3, acc[r][3]);
            }
        }
    }
    #pragma unroll
    for(int r=0; r<4; r++){
        int m = m0 + tm + 16*r;
        #pragma unroll
        for(int p=0; p<4; p++){
            int n = n0 + tn*8 + 2*p;
            float2 vv = up2(acc[r][p]);
            vv.x += bo[n]; vv.y += bo[n+1];
            *(float2*)&out[(size_t)m*CC + n] = vv;
        }
    }
}

// ------------------------- launch (serial; attn at profiled idx 3) ----------
extern "C" void kernel_launch(void* const* d_in, const int* in_sizes, int n_in,
                              void* d_out, int out_size){
    const float* a     = (const float*)d_in[0];
    const float* z     = (const float*)d_in[1];
    const float* mask  = (const float*)d_in[2];
    const float* lnaw  = (const float*)d_in[3];
    const float* lnab  = (const float*)d_in[4];
    const float* lnzw  = (const float*)d_in[5];
    const float* lnzb  = (const float*)d_in[6];
    const float* Wz    = (const float*)d_in[7];
    const float* Wq    = (const float*)d_in[8];
    const float* Wk    = (const float*)d_in[9];
    const float* Wv    = (const float*)d_in[10];
    const float* Wg    = (const float*)d_in[11];
    const float* bg    = (const float*)d_in[12];
    const float* Wo    = (const float*)d_in[13];
    const float* bo    = (const float*)d_in[14];
    float* out = (float*)d_out;

    k_lnaprep<<<97, 256>>>(a, lnaw, lnab, lnzw, lnzb, Wz);               // 0
    k_proj<<<dim3(6, 12, 4), 128>>>(Wq, Wk, Wv, Wg, bg);                 // 1
    k_bias<<<dim3(6, 768), 128>>>(z);                                    // 2
    k_attn<<<dim3(24, 16), 256>>>(mask);                                 // 3 (profiled)
    k_oproj<<<dim3(6, 12), 128>>>(Wo, bo, out);                          // 4
}